// round 1
// baseline (speedup 1.0000x reference)
#include <cuda_runtime.h>
#include <cuda_bf16.h>
#include <cstdint>
#include <cstddef>

// ----------------------------------------------------------------------------
// Transformer attention, B=4, S=2048, D=1024, DIM_QK=1024.
// All GEMMs done in bf16 split precision (hi/lo) with K'=3K trick:
//   A' = [hi | lo | hi],  B' = [hi | hi | lo]  =>  sum = hh + lh + hl  (~fp32)
// Substrate: mma.sync.m16n8k16 bf16 (round-0 baseline; tcgen05 later).
// ----------------------------------------------------------------------------

#define S_LEN   2048
#define DMODEL  1024
#define BATCH   4
#define MTOT    8192            // B*S
#define K1      3072            // 3*DMODEL
#define K2      6144            // 3*S_LEN

// ---------------- scratch (static device memory; no allocs) ----------------
__device__ __nv_bfloat16 g_x2   [(size_t)MTOT  * K1];   // 50 MB
__device__ __nv_bfloat16 g_Wall2[(size_t)3072  * K1];   // 19 MB
__device__ __nv_bfloat16 g_Wo2  [(size_t)1024  * K1];   //  6 MB
__device__ float         g_QKV  [(size_t)MTOT  * 3072]; // 100 MB
__device__ __nv_bfloat16 g_q2   [(size_t)MTOT  * K1];   // 50 MB
__device__ __nv_bfloat16 g_k2   [(size_t)MTOT  * K1];   // 50 MB
__device__ __nv_bfloat16 g_v2T  [(size_t)BATCH * DMODEL * K2]; // 50 MB
__device__ __nv_bfloat16 g_attn2[(size_t)BATCH * S_LEN  * K2]; // 100 MB
__device__ float         g_ctx  [(size_t)MTOT  * DMODEL];      // 33 MB
__device__ __nv_bfloat16 g_ctx2 [(size_t)MTOT  * K1];          // 50 MB

// ---------------- PTX helpers ----------------
__device__ __forceinline__ void mma16816(float c[4], const uint32_t a[4], const uint32_t b[2]) {
    asm volatile(
        "mma.sync.aligned.m16n8k16.row.col.f32.bf16.bf16.f32 "
        "{%0,%1,%2,%3}, {%4,%5,%6,%7}, {%8,%9}, {%0,%1,%2,%3};\n"
        : "+f"(c[0]), "+f"(c[1]), "+f"(c[2]), "+f"(c[3])
        : "r"(a[0]), "r"(a[1]), "r"(a[2]), "r"(a[3]), "r"(b[0]), "r"(b[1]));
}

__device__ __forceinline__ void ldsm_x4(uint32_t r[4], uint32_t addr) {
    asm volatile("ldmatrix.sync.aligned.m8n8.x4.shared.b16 {%0,%1,%2,%3}, [%4];\n"
                 : "=r"(r[0]), "=r"(r[1]), "=r"(r[2]), "=r"(r[3]) : "r"(addr));
}

__device__ __forceinline__ void cp16(uint32_t s, const void* g) {
    asm volatile("cp.async.cg.shared.global [%0], [%1], 16;\n" :: "r"(s), "l"(g));
}
#define CP_COMMIT() asm volatile("cp.async.commit_group;\n" ::: "memory")

// ---------------- generic bf16 GEMM: C[M,N] = scale * A[M,K] @ B[N,K]^T -----
// A, B row-major with ld = K (K-contiguous); C row-major ld = N.
// BM=BN=128, BK=32, 256 threads, warp tile 64x32.
#define BM 128
#define BN 128
#define BK 32
#define SROW 80                     // 32 bf16 = 64B data + 16B pad (conflict-free)
#define BUFSZ ((BM + BN) * SROW)    // 20480 B per stage

__global__ __launch_bounds__(256, 2)
void gemm_bf16_kernel(const __nv_bfloat16* __restrict__ A,
                      const __nv_bfloat16* __restrict__ B,
                      float* __restrict__ C,
                      int K, int N,
                      long long strideA, long long strideB, long long strideC,
                      float scale)
{
    __shared__ __align__(16) unsigned char smem[2 * BUFSZ];   // 40 KB

    const int b = blockIdx.z;
    A += (size_t)b * strideA;
    B += (size_t)b * strideB;
    C += (size_t)b * strideC;

    const int bm  = blockIdx.y * BM;
    const int bn  = blockIdx.x * BN;
    const int tid = threadIdx.x;

    const uint32_t sbase = (uint32_t)__cvta_generic_to_shared(smem);

    // global -> smem mapping: 256 threads cover 64 rows x 4 chunks; 2 row passes
    const int ldrow   = tid >> 2;         // 0..63
    const int ldchunk = tid & 3;          // 16B chunk within 32-col (bf16) row
    const __nv_bfloat16* Ag = A + (size_t)(bm + ldrow) * K + ldchunk * 8;
    const __nv_bfloat16* Bg = B + (size_t)(bn + ldrow) * K + ldchunk * 8;
    const uint32_t sA0 = sbase + ldrow * SROW + ldchunk * 16;
    const uint32_t sB0 = sA0 + BM * SROW;

    const int KT = K / BK;

    auto issue = [&](int kt, int buf) {
        const __nv_bfloat16* ag = Ag + (size_t)kt * BK;
        const __nv_bfloat16* bg = Bg + (size_t)kt * BK;
        uint32_t off = buf * BUFSZ;
        cp16(sA0 + off,             ag);
        cp16(sA0 + off + 64 * SROW, ag + (size_t)64 * K);
        cp16(sB0 + off,             bg);
        cp16(sB0 + off + 64 * SROW, bg + (size_t)64 * K);
    };

    const int warp = tid >> 5;
    const int lane = tid & 31;
    const int wm = (warp >> 2) * 64;      // 2 warps along M
    const int wn = (warp & 3) * 32;       // 4 warps along N

    float acc[4][4][4];
    #pragma unroll
    for (int i = 0; i < 4; i++)
        #pragma unroll
        for (int j = 0; j < 4; j++)
            #pragma unroll
            for (int k = 0; k < 4; k++) acc[i][j][k] = 0.0f;

    issue(0, 0); CP_COMMIT();

    for (int kt = 0; kt < KT; kt++) {
        if (kt + 1 < KT) {
            issue(kt + 1, (kt + 1) & 1); CP_COMMIT();
            asm volatile("cp.async.wait_group 1;\n" ::: "memory");
        } else {
            asm volatile("cp.async.wait_group 0;\n" ::: "memory");
        }
        __syncthreads();

        const uint32_t aTile = sbase + (kt & 1) * BUFSZ;
        const uint32_t bTile = aTile + BM * SROW;

        #pragma unroll
        for (int ks = 0; ks < 2; ks++) {              // two k16 steps per BK=32
            uint32_t ra[4][4];
            #pragma unroll
            for (int mi = 0; mi < 4; mi++) {
                int r  = wm + mi * 16 + (lane & 15);
                int ch = ks * 2 + (lane >> 4);
                ldsm_x4(ra[mi], aTile + r * SROW + ch * 16);
            }
            uint32_t rb[2][4];
            #pragma unroll
            for (int np = 0; np < 2; np++) {
                int n  = wn + np * 16 + (lane & 7) + ((lane & 16) >> 1);
                int ch = ks * 2 + ((lane >> 3) & 1);
                ldsm_x4(rb[np], bTile + n * SROW + ch * 16);
            }
            #pragma unroll
            for (int mi = 0; mi < 4; mi++)
                #pragma unroll
                for (int ni = 0; ni < 4; ni++)
                    mma16816(acc[mi][ni], ra[mi], &rb[ni >> 1][(ni & 1) * 2]);
        }
        __syncthreads();
    }

    // epilogue
    #pragma unroll
    for (int mi = 0; mi < 4; mi++) {
        int r0 = bm + wm + mi * 16 + (lane >> 2);
        #pragma unroll
        for (int ni = 0; ni < 4; ni++) {
            int c = bn + wn + ni * 8 + (lane & 3) * 2;
            float* p0 = C + (size_t)r0 * N + c;
            p0[0] = acc[mi][ni][0] * scale;
            p0[1] = acc[mi][ni][1] * scale;
            float* p1 = p0 + (size_t)8 * N;
            p1[0] = acc[mi][ni][2] * scale;
            p1[1] = acc[mi][ni][3] * scale;
        }
    }
}

// ---------------- split-precision conversion ----------------
// mode 0 (A-side): dst[k]=hi, dst[K+k]=lo, dst[2K+k]=hi
// mode 1 (B-side): dst[k]=hi, dst[K+k]=hi, dst[2K+k]=lo
__global__ void conv_split_kernel(const float* __restrict__ src,
                                  __nv_bfloat16* __restrict__ dst,
                                  int n, int K, int srcLd, int mode)
{
    int i = blockIdx.x * blockDim.x + threadIdx.x;
    if (i >= n) return;
    int row = i / K;
    int k   = i - row * K;
    float a = src[(size_t)row * srcLd + k];
    __nv_bfloat16 hi = __float2bfloat16(a);
    __nv_bfloat16 lo = __float2bfloat16(a - __bfloat162float(hi));
    __nv_bfloat16* d = dst + (size_t)row * (3 * K) + k;
    if (mode == 0) { d[0] = hi; d[K] = lo; d[2 * K] = hi; }
    else           { d[0] = hi; d[K] = hi; d[2 * K] = lo; }
}

// V transpose + split (B-side pattern):  v2T[b][j][t | 2048+t | 4096+t]
__global__ void conv_vT_kernel(const float* __restrict__ qkv,
                               __nv_bfloat16* __restrict__ v2T)
{
    __shared__ float tile[32][33];
    const int b  = blockIdx.z;
    const int t0 = blockIdx.x * 32;
    const int j0 = blockIdx.y * 32;
    const int tx = threadIdx.x, ty = threadIdx.y;   // 32 x 8

    #pragma unroll
    for (int i = 0; i < 32; i += 8)
        tile[ty + i][tx] = qkv[((size_t)(b * S_LEN + t0 + ty + i)) * 3072 + 2048 + j0 + tx];
    __syncthreads();

    #pragma unroll
    for (int i = 0; i < 32; i += 8) {
        int j = j0 + ty + i;
        int t = t0 + tx;
        float a = tile[tx][ty + i];
        __nv_bfloat16 hi = __float2bfloat16(a);
        __nv_bfloat16 lo = __float2bfloat16(a - __bfloat162float(hi));
        __nv_bfloat16* d = v2T + ((size_t)b * DMODEL + j) * K2 + t;
        d[0] = hi; d[S_LEN] = hi; d[2 * S_LEN] = lo;
    }
}

// softmax over rows of dist (already scaled), write attn as A-side split bf16
__global__ void softmax_kernel(const float* __restrict__ dist,
                               __nv_bfloat16* __restrict__ attn2)
{
    const int row = blockIdx.x;                   // 0..8191
    const float* d = dist + (size_t)row * S_LEN;
    const int tid = threadIdx.x;                  // 256

    float vals[8];
    float m = -1e30f;
    #pragma unroll
    for (int i = 0; i < 8; i++) { vals[i] = d[tid + i * 256]; m = fmaxf(m, vals[i]); }

    __shared__ float red[8];
    #pragma unroll
    for (int o = 16; o; o >>= 1) m = fmaxf(m, __shfl_xor_sync(0xffffffffu, m, o));
    if ((tid & 31) == 0) red[tid >> 5] = m;
    __syncthreads();
    m = red[0];
    #pragma unroll
    for (int i = 1; i < 8; i++) m = fmaxf(m, red[i]);
    __syncthreads();

    float s = 0.0f;
    #pragma unroll
    for (int i = 0; i < 8; i++) { vals[i] = expf(vals[i] - m); s += vals[i]; }
    #pragma unroll
    for (int o = 16; o; o >>= 1) s += __shfl_xor_sync(0xffffffffu, s, o);
    if ((tid & 31) == 0) red[tid >> 5] = s;
    __syncthreads();
    float tot = 0.0f;
    #pragma unroll
    for (int i = 0; i < 8; i++) tot += red[i];
    const float inv = 1.0f / tot;

    __nv_bfloat16* a2 = attn2 + (size_t)row * K2;
    #pragma unroll
    for (int i = 0; i < 8; i++) {
        int t = tid + i * 256;
        float p = vals[i] * inv;
        __nv_bfloat16 hi = __float2bfloat16(p);
        __nv_bfloat16 lo = __float2bfloat16(p - __bfloat162float(hi));
        a2[t] = hi; a2[S_LEN + t] = lo; a2[2 * S_LEN + t] = hi;
    }
}

// ---------------- launch ----------------
extern "C" void kernel_launch(void* const* d_in, const int* in_sizes, int n_in,
                              void* d_out, int out_size)
{
    (void)in_sizes; (void)n_in; (void)out_size;
    const float* x  = (const float*)d_in[0];
    const float* Wq = (const float*)d_in[1];
    const float* Wk = (const float*)d_in[2];
    const float* Wv = (const float*)d_in[3];
    const float* Wo = (const float*)d_in[4];

    float* out    = (float*)d_out;                               // [4,2048,1024]
    float* weight = out + (size_t)MTOT * DMODEL;                 // [4,2048,2048]

    void *p_x2, *p_Wall2, *p_Wo2, *p_QKV, *p_q2, *p_k2, *p_v2T, *p_attn2, *p_ctx, *p_ctx2;
    cudaGetSymbolAddress(&p_x2,    g_x2);
    cudaGetSymbolAddress(&p_Wall2, g_Wall2);
    cudaGetSymbolAddress(&p_Wo2,   g_Wo2);
    cudaGetSymbolAddress(&p_QKV,   g_QKV);
    cudaGetSymbolAddress(&p_q2,    g_q2);
    cudaGetSymbolAddress(&p_k2,    g_k2);
    cudaGetSymbolAddress(&p_v2T,   g_v2T);
    cudaGetSymbolAddress(&p_attn2, g_attn2);
    cudaGetSymbolAddress(&p_ctx,   g_ctx);
    cudaGetSymbolAddress(&p_ctx2,  g_ctx2);

    __nv_bfloat16* x2    = (__nv_bfloat16*)p_x2;
    __nv_bfloat16* Wall2 = (__nv_bfloat16*)p_Wall2;
    __nv_bfloat16* Wo2   = (__nv_bfloat16*)p_Wo2;
    float*         QKV   = (float*)p_QKV;
    __nv_bfloat16* q2    = (__nv_bfloat16*)p_q2;
    __nv_bfloat16* k2    = (__nv_bfloat16*)p_k2;
    __nv_bfloat16* v2T   = (__nv_bfloat16*)p_v2T;
    __nv_bfloat16* attn2 = (__nv_bfloat16*)p_attn2;
    float*         ctx   = (float*)p_ctx;
    __nv_bfloat16* ctx2  = (__nv_bfloat16*)p_ctx2;

    const int CT = 256;
    const float dist_scale = 0.044194173824159223f;   // (1024/2)^-0.5

    // 1) split-convert inputs
    conv_split_kernel<<<(MTOT * DMODEL + CT - 1) / CT, CT>>>(x, x2, MTOT * DMODEL, DMODEL, DMODEL, 0);
    conv_split_kernel<<<(1024 * 1024 + CT - 1) / CT, CT>>>(Wq, Wall2,                          1024 * 1024, 1024, 1024, 1);
    conv_split_kernel<<<(1024 * 1024 + CT - 1) / CT, CT>>>(Wk, Wall2 + (size_t)1024 * K1,      1024 * 1024, 1024, 1024, 1);
    conv_split_kernel<<<(1024 * 1024 + CT - 1) / CT, CT>>>(Wv, Wall2 + (size_t)2048 * K1,      1024 * 1024, 1024, 1024, 1);
    conv_split_kernel<<<(1024 * 1024 + CT - 1) / CT, CT>>>(Wo, Wo2,                            1024 * 1024, 1024, 1024, 1);

    // 2) QKV = x @ [Wq;Wk;Wv]^T   [8192 x 3072]
    gemm_bf16_kernel<<<dim3(3072 / BN, MTOT / BM, 1), 256>>>(
        x2, Wall2, QKV, K1, 3072, 0, 0, 0, 1.0f);

    // 3) split q, k; transpose+split v
    conv_split_kernel<<<(MTOT * 1024 + CT - 1) / CT, CT>>>(QKV,        q2, MTOT * 1024, 1024, 3072, 0);
    conv_split_kernel<<<(MTOT * 1024 + CT - 1) / CT, CT>>>(QKV + 1024, k2, MTOT * 1024, 1024, 3072, 1);
    conv_vT_kernel<<<dim3(S_LEN / 32, DMODEL / 32, BATCH), dim3(32, 8)>>>(QKV, v2T);

    // 4) dist = scale * q @ k^T  -> weight region of d_out  [4][2048][2048]
    gemm_bf16_kernel<<<dim3(S_LEN / BN, S_LEN / BM, BATCH), 256>>>(
        q2, k2, weight, K1, S_LEN,
        (long long)S_LEN * K1, (long long)S_LEN * K1, (long long)S_LEN * S_LEN,
        dist_scale);

    // 5) softmax rows -> attn (split bf16)
    softmax_kernel<<<MTOT, 256>>>(weight, attn2);

    // 6) ctx = attn @ v   [2048 x 1024] per batch
    gemm_bf16_kernel<<<dim3(DMODEL / BN, S_LEN / BM, BATCH), 256>>>(
        attn2, v2T, ctx, K2, DMODEL,
        (long long)S_LEN * K2, (long long)DMODEL * K2, (long long)S_LEN * DMODEL,
        1.0f);

    // 7) out = ctx @ Wo^T  [8192 x 1024]
    conv_split_kernel<<<(MTOT * DMODEL + CT - 1) / CT, CT>>>(ctx, ctx2, MTOT * DMODEL, DMODEL, DMODEL, 0);
    gemm_bf16_kernel<<<dim3(DMODEL / BN, MTOT / BM, 1), 256>>>(
        ctx2, Wo2, out, K1, DMODEL, 0, 0, 0, 1.0f);
}

// round 3
// speedup vs baseline: 1.1148x; 1.1148x over previous
#include <cuda_runtime.h>
#include <cuda_bf16.h>
#include <cstdint>
#include <cstddef>

// ----------------------------------------------------------------------------
// Transformer attention, B=4, S=2048, D=1024.  Split-bf16 (K'=3K) GEMMs on
// mma.sync.m16n8k16 (ptxas target rejects tcgen05).  128x256x32 CTA tile,
// 64x64 warp tile, 4-stage cp.async pipeline, fused split epilogues.
// ----------------------------------------------------------------------------

#define S_LEN   2048
#define DMODEL  1024
#define BATCH   4
#define MTOT    8192
#define K1      3072
#define K2      6144

// ---------------- scratch ----------------
__device__ __nv_bfloat16 g_x2   [(size_t)MTOT  * K1];
__device__ __nv_bfloat16 g_Wall2[(size_t)3072  * K1];
__device__ __nv_bfloat16 g_Wo2  [(size_t)1024  * K1];
__device__ __nv_bfloat16 g_q2   [(size_t)MTOT  * K1];
__device__ __nv_bfloat16 g_k2   [(size_t)MTOT  * K1];
__device__ float         g_vbuf [(size_t)MTOT  * DMODEL];
__device__ __nv_bfloat16 g_v2T  [(size_t)BATCH * DMODEL * K2];
__device__ __nv_bfloat16 g_attn2[(size_t)BATCH * S_LEN  * K2];
__device__ __nv_bfloat16 g_ctx2 [(size_t)MTOT  * K1];

// ---------------- PTX helpers ----------------
__device__ __forceinline__ void mma16816(float c[4], const uint32_t a[4], const uint32_t b[2]) {
    asm volatile(
        "mma.sync.aligned.m16n8k16.row.col.f32.bf16.bf16.f32 "
        "{%0,%1,%2,%3}, {%4,%5,%6,%7}, {%8,%9}, {%0,%1,%2,%3};\n"
        : "+f"(c[0]), "+f"(c[1]), "+f"(c[2]), "+f"(c[3])
        : "r"(a[0]), "r"(a[1]), "r"(a[2]), "r"(a[3]), "r"(b[0]), "r"(b[1]));
}
__device__ __forceinline__ void ldsm_x4(uint32_t r[4], uint32_t addr) {
    asm volatile("ldmatrix.sync.aligned.m8n8.x4.shared.b16 {%0,%1,%2,%3}, [%4];\n"
                 : "=r"(r[0]), "=r"(r[1]), "=r"(r[2]), "=r"(r[3]) : "r"(addr));
}
__device__ __forceinline__ void cp16(uint32_t s, const void* g) {
    asm volatile("cp.async.cg.shared.global [%0], [%1], 16;\n" :: "r"(s), "l"(g));
}
#define CP_COMMIT()     asm volatile("cp.async.commit_group;\n" ::: "memory")
#define CP_WAIT(n)      asm volatile("cp.async.wait_group %0;\n" :: "n"(n) : "memory")

__device__ __forceinline__ uint32_t pk2(__nv_bfloat16 a, __nv_bfloat16 b) {
    return (uint32_t)__bfloat16_as_ushort(a) | ((uint32_t)__bfloat16_as_ushort(b) << 16);
}

// ---------------- GEMM: C[M,N] = op(scale * A[M,K] @ B[N,K]^T) --------------
// A,B row-major bf16, ld=K.  128x256x32 tile, 256 threads, warp tile 64x64.
// mode 0: fp32 out (ld N, *scale)
// mode 1: split-A bf16 out [hi|lo|hi], dst ld 3N
// mode 2: QKV fused: cols [0,1024) -> q2 split-A; [1024,2048) -> k2 split-B;
//         [2048,3072) -> vbuf fp32 (ld 1024)
#define BM 128
#define BN 256
#define BK 32
#define NSTG 4
#define SROW 80
#define A_BYTES (BM * SROW)               // 10240
#define STAGE_BYTES ((BM + BN) * SROW)    // 30720
#define GEMM_SMEM (NSTG * STAGE_BYTES)    // 122880

__global__ __launch_bounds__(256, 1)
void gemm_bf16(const __nv_bfloat16* __restrict__ A,
               const __nv_bfloat16* __restrict__ B,
               void* __restrict__ Cout,
               __nv_bfloat16* __restrict__ q2,
               __nv_bfloat16* __restrict__ k2,
               float* __restrict__ vbuf,
               int K, int N,
               long long strideA, long long strideB, long long strideC,
               float scale, int mode)
{
    extern __shared__ __align__(16) unsigned char smem[];
    const uint32_t sbase = (uint32_t)__cvta_generic_to_shared(smem);

    const int b = blockIdx.z;
    A += (size_t)b * strideA;
    B += (size_t)b * strideB;

    const int bm = blockIdx.y * BM;
    const int bn = blockIdx.x * BN;
    const int tid = threadIdx.x;
    const int KT = K / BK;

    // producer mapping: 256 threads, rows tid>>2, 16B chunk tid&3
    const int prow = tid >> 2;            // 0..63
    const int pch  = tid & 3;
    const __nv_bfloat16* Ag = A + (size_t)(bm + prow) * K + pch * 8;
    const __nv_bfloat16* Bg = B + (size_t)(bn + prow) * K + pch * 8;
    const uint32_t sA = sbase + prow * SROW + pch * 16;
    const uint32_t sB = sbase + A_BYTES + prow * SROW + pch * 16;

    auto issue = [&](int kt) {
        const uint32_t st = (kt & (NSTG - 1)) * STAGE_BYTES;
        const size_t go = (size_t)kt * BK;
        cp16(sA + st,             Ag + go);
        cp16(sA + st + 64 * SROW, Ag + go + (size_t)64 * K);
        #pragma unroll
        for (int p = 0; p < 4; p++)
            cp16(sB + st + p * 64 * SROW, Bg + go + (size_t)(p * 64) * K);
    };

    const int warp = tid >> 5;
    const int lane = tid & 31;
    const int wm = (warp & 1) * 64;
    const int wn = (warp >> 1) * 64;

    float acc[4][8][4];
    #pragma unroll
    for (int i = 0; i < 4; i++)
        #pragma unroll
        for (int j = 0; j < 8; j++)
            #pragma unroll
            for (int k = 0; k < 4; k++) acc[i][j][k] = 0.0f;

    issue(0); CP_COMMIT();
    issue(1); CP_COMMIT();
    issue(2); CP_COMMIT();

    // precompute ldsm base offsets (within a stage)
    const uint32_t aOff = (wm + (lane & 15)) * SROW + (lane >> 4) * 16;
    const uint32_t bOff = A_BYTES + (wn + (lane & 7) + ((lane & 16) >> 1)) * SROW
                        + ((lane >> 3) & 1) * 16;

    for (int kt = 0; kt < KT; kt++) {
        CP_WAIT(2);
        __syncthreads();
        if (kt + 3 < KT) issue(kt + 3);
        CP_COMMIT();

        const uint32_t st = sbase + (kt & (NSTG - 1)) * STAGE_BYTES;
        #pragma unroll
        for (int ks = 0; ks < 2; ks++) {
            uint32_t ra[4][4], rb[4][4];
            #pragma unroll
            for (int mi = 0; mi < 4; mi++)
                ldsm_x4(ra[mi], st + aOff + mi * 16 * SROW + ks * 32);
            #pragma unroll
            for (int np = 0; np < 4; np++)
                ldsm_x4(rb[np], st + bOff + np * 16 * SROW + ks * 32);
            #pragma unroll
            for (int mi = 0; mi < 4; mi++)
                #pragma unroll
                for (int ni = 0; ni < 8; ni++)
                    mma16816(acc[mi][ni], ra[mi], &rb[ni >> 1][(ni & 1) * 2]);
        }
    }

    // ---------------- epilogue ----------------
    #pragma unroll
    for (int mi = 0; mi < 4; mi++) {
        const int r0 = bm + wm + mi * 16 + (lane >> 2);
        #pragma unroll
        for (int ni = 0; ni < 8; ni++) {
            const int cl = wn + ni * 8 + (lane & 3) * 2;   // 0..255
            float v00 = acc[mi][ni][0], v01 = acc[mi][ni][1];
            float v10 = acc[mi][ni][2], v11 = acc[mi][ni][3];
            if (mode == 0) {
                float* C = (float*)Cout + (size_t)b * strideC;
                float2* p0 = (float2*)(C + (size_t)r0 * N + bn + cl);
                float2* p1 = (float2*)(C + (size_t)(r0 + 8) * N + bn + cl);
                *p0 = make_float2(v00 * scale, v01 * scale);
                *p1 = make_float2(v10 * scale, v11 * scale);
            } else if (mode == 1) {
                __nv_bfloat16* D = (__nv_bfloat16*)Cout + (size_t)b * strideC;
                #pragma unroll
                for (int rr = 0; rr < 2; rr++) {
                    float a0 = rr ? v10 : v00, a1 = rr ? v11 : v01;
                    __nv_bfloat16 h0 = __float2bfloat16(a0), h1 = __float2bfloat16(a1);
                    __nv_bfloat16 l0 = __float2bfloat16(a0 - __bfloat162float(h0));
                    __nv_bfloat16 l1 = __float2bfloat16(a1 - __bfloat162float(h1));
                    __nv_bfloat16* d = D + (size_t)(r0 + rr * 8) * (3 * N) + bn + cl;
                    *(uint32_t*)d           = pk2(h0, h1);
                    *(uint32_t*)(d + N)     = pk2(l0, l1);
                    *(uint32_t*)(d + 2 * N) = pk2(h0, h1);
                }
            } else {
                const int g = bn + cl;
                const int region = g >> 10;
                const int c = g & 1023;
                #pragma unroll
                for (int rr = 0; rr < 2; rr++) {
                    float a0 = rr ? v10 : v00, a1 = rr ? v11 : v01;
                    const size_t row = (size_t)(r0 + rr * 8);
                    if (region == 2) {
                        *(float2*)(vbuf + row * 1024 + c) = make_float2(a0, a1);
                    } else {
                        __nv_bfloat16 h0 = __float2bfloat16(a0), h1 = __float2bfloat16(a1);
                        __nv_bfloat16 l0 = __float2bfloat16(a0 - __bfloat162float(h0));
                        __nv_bfloat16 l1 = __float2bfloat16(a1 - __bfloat162float(h1));
                        if (region == 0) {            // q2: [hi | lo | hi]
                            __nv_bfloat16* d = q2 + row * 3072 + c;
                            *(uint32_t*)d            = pk2(h0, h1);
                            *(uint32_t*)(d + 1024)   = pk2(l0, l1);
                            *(uint32_t*)(d + 2048)   = pk2(h0, h1);
                        } else {                      // k2: [hi | hi | lo]
                            __nv_bfloat16* d = k2 + row * 3072 + c;
                            *(uint32_t*)d            = pk2(h0, h1);
                            *(uint32_t*)(d + 1024)   = pk2(h0, h1);
                            *(uint32_t*)(d + 2048)   = pk2(l0, l1);
                        }
                    }
                }
            }
        }
    }
}

// ---------------- vectorized split conversion ----------------
// mode 0 (A-side): [hi | lo | hi]   mode 1 (B-side): [hi | hi | lo]
__global__ void conv_split4(const float* __restrict__ src,
                            __nv_bfloat16* __restrict__ dst,
                            int n4, int K, int srcLd, int mode)
{
    int i = blockIdx.x * blockDim.x + threadIdx.x;
    if (i >= n4) return;
    int idx = i * 4;
    int row = idx / K;
    int k   = idx - row * K;
    float4 a = *(const float4*)(src + (size_t)row * srcLd + k);
    __nv_bfloat16 h0 = __float2bfloat16(a.x), h1 = __float2bfloat16(a.y);
    __nv_bfloat16 h2 = __float2bfloat16(a.z), h3 = __float2bfloat16(a.w);
    __nv_bfloat16 l0 = __float2bfloat16(a.x - __bfloat162float(h0));
    __nv_bfloat16 l1 = __float2bfloat16(a.y - __bfloat162float(h1));
    __nv_bfloat16 l2 = __float2bfloat16(a.z - __bfloat162float(h2));
    __nv_bfloat16 l3 = __float2bfloat16(a.w - __bfloat162float(h3));
    uint2 H = make_uint2(pk2(h0, h1), pk2(h2, h3));
    uint2 L = make_uint2(pk2(l0, l1), pk2(l2, l3));
    __nv_bfloat16* d = dst + (size_t)row * (3 * K) + k;
    *(uint2*)d           = H;
    *(uint2*)(d + K)     = (mode == 0) ? L : H;
    *(uint2*)(d + 2 * K) = (mode == 0) ? H : L;
}

// V transpose + split (B-side):  v2T[b][j][t | 2048+t | 4096+t]
__global__ void conv_vT_kernel(const float* __restrict__ vbuf,
                               __nv_bfloat16* __restrict__ v2T)
{
    __shared__ float tile[32][33];
    const int b  = blockIdx.z;
    const int t0 = blockIdx.x * 32;
    const int j0 = blockIdx.y * 32;
    const int tx = threadIdx.x, ty = threadIdx.y;   // 32 x 8

    #pragma unroll
    for (int i = 0; i < 32; i += 8)
        tile[ty + i][tx] = vbuf[((size_t)(b * S_LEN + t0 + ty + i)) * DMODEL + j0 + tx];
    __syncthreads();

    #pragma unroll
    for (int i = 0; i < 32; i += 8) {
        int j = j0 + ty + i;
        int t = t0 + tx;
        float a = tile[tx][ty + i];
        __nv_bfloat16 hi = __float2bfloat16(a);
        __nv_bfloat16 lo = __float2bfloat16(a - __bfloat162float(hi));
        __nv_bfloat16* d = v2T + ((size_t)b * DMODEL + j) * K2 + t;
        d[0] = hi; d[S_LEN] = hi; d[2 * S_LEN] = lo;
    }
}

// softmax over rows of dist (already scaled); write attn split (A-side)
__global__ void softmax_kernel(const float* __restrict__ dist,
                               __nv_bfloat16* __restrict__ attn2)
{
    const int row = blockIdx.x;
    const int tid = threadIdx.x;                  // 256
    const float4* d4 = (const float4*)(dist + (size_t)row * S_LEN) + tid * 2;
    float4 v0 = d4[0], v1 = d4[1];
    float v[8] = {v0.x, v0.y, v0.z, v0.w, v1.x, v1.y, v1.z, v1.w};

    float m = v[0];
    #pragma unroll
    for (int i = 1; i < 8; i++) m = fmaxf(m, v[i]);
    __shared__ float red[8];
    #pragma unroll
    for (int o = 16; o; o >>= 1) m = fmaxf(m, __shfl_xor_sync(0xffffffffu, m, o));
    if ((tid & 31) == 0) red[tid >> 5] = m;
    __syncthreads();
    m = red[0];
    #pragma unroll
    for (int i = 1; i < 8; i++) m = fmaxf(m, red[i]);
    __syncthreads();

    float s = 0.0f;
    #pragma unroll
    for (int i = 0; i < 8; i++) { v[i] = __expf(v[i] - m); s += v[i]; }
    #pragma unroll
    for (int o = 16; o; o >>= 1) s += __shfl_xor_sync(0xffffffffu, s, o);
    if ((tid & 31) == 0) red[tid >> 5] = s;
    __syncthreads();
    float tot = 0.0f;
    #pragma unroll
    for (int i = 0; i < 8; i++) tot += red[i];
    const float inv = 1.0f / tot;

    uint32_t H[4], L[4];
    #pragma unroll
    for (int i = 0; i < 4; i++) {
        float p0 = v[2 * i] * inv, p1 = v[2 * i + 1] * inv;
        __nv_bfloat16 h0 = __float2bfloat16(p0), h1 = __float2bfloat16(p1);
        __nv_bfloat16 l0 = __float2bfloat16(p0 - __bfloat162float(h0));
        __nv_bfloat16 l1 = __float2bfloat16(p1 - __bfloat162float(h1));
        H[i] = pk2(h0, h1); L[i] = pk2(l0, l1);
    }
    __nv_bfloat16* a2 = attn2 + (size_t)row * K2 + tid * 8;
    *(uint4*)(a2)             = make_uint4(H[0], H[1], H[2], H[3]);
    *(uint4*)(a2 + S_LEN)     = make_uint4(L[0], L[1], L[2], L[3]);
    *(uint4*)(a2 + 2 * S_LEN) = make_uint4(H[0], H[1], H[2], H[3]);
}

// ---------------- launch ----------------
extern "C" void kernel_launch(void* const* d_in, const int* in_sizes, int n_in,
                              void* d_out, int out_size)
{
    (void)in_sizes; (void)n_in; (void)out_size;
    const float* x  = (const float*)d_in[0];
    const float* Wq = (const float*)d_in[1];
    const float* Wk = (const float*)d_in[2];
    const float* Wv = (const float*)d_in[3];
    const float* Wo = (const float*)d_in[4];

    float* out    = (float*)d_out;                       // [4,2048,1024]
    float* weight = out + (size_t)MTOT * DMODEL;         // [4,2048,2048]

    void *p_x2, *p_Wall2, *p_Wo2, *p_q2, *p_k2, *p_vbuf, *p_v2T, *p_attn2, *p_ctx2;
    cudaGetSymbolAddress(&p_x2,    g_x2);
    cudaGetSymbolAddress(&p_Wall2, g_Wall2);
    cudaGetSymbolAddress(&p_Wo2,   g_Wo2);
    cudaGetSymbolAddress(&p_q2,    g_q2);
    cudaGetSymbolAddress(&p_k2,    g_k2);
    cudaGetSymbolAddress(&p_vbuf,  g_vbuf);
    cudaGetSymbolAddress(&p_v2T,   g_v2T);
    cudaGetSymbolAddress(&p_attn2, g_attn2);
    cudaGetSymbolAddress(&p_ctx2,  g_ctx2);

    __nv_bfloat16* x2    = (__nv_bfloat16*)p_x2;
    __nv_bfloat16* Wall2 = (__nv_bfloat16*)p_Wall2;
    __nv_bfloat16* Wo2   = (__nv_bfloat16*)p_Wo2;
    __nv_bfloat16* q2    = (__nv_bfloat16*)p_q2;
    __nv_bfloat16* k2    = (__nv_bfloat16*)p_k2;
    float*         vbuf  = (float*)p_vbuf;
    __nv_bfloat16* v2T   = (__nv_bfloat16*)p_v2T;
    __nv_bfloat16* attn2 = (__nv_bfloat16*)p_attn2;
    __nv_bfloat16* ctx2  = (__nv_bfloat16*)p_ctx2;

    cudaFuncSetAttribute(gemm_bf16, cudaFuncAttributeMaxDynamicSharedMemorySize, GEMM_SMEM);

    const int CT = 256;
    const float dist_scale = 0.044194173824159223f;   // (1024/2)^-0.5

    // 1) split-convert inputs
    conv_split4<<<(MTOT * DMODEL / 4 + CT - 1) / CT, CT>>>(x, x2, MTOT * DMODEL / 4, DMODEL, DMODEL, 0);
    conv_split4<<<(1024 * 1024 / 4 + CT - 1) / CT, CT>>>(Wq, Wall2,                     1024 * 1024 / 4, 1024, 1024, 1);
    conv_split4<<<(1024 * 1024 / 4 + CT - 1) / CT, CT>>>(Wk, Wall2 + (size_t)1024 * K1, 1024 * 1024 / 4, 1024, 1024, 1);
    conv_split4<<<(1024 * 1024 / 4 + CT - 1) / CT, CT>>>(Wv, Wall2 + (size_t)2048 * K1, 1024 * 1024 / 4, 1024, 1024, 1);
    conv_split4<<<(1024 * 1024 / 4 + CT - 1) / CT, CT>>>(Wo, Wo2,                       1024 * 1024 / 4, 1024, 1024, 1);

    // 2) QKV fused: x2 @ Wall2^T -> q2 (split-A), k2 (split-B), vbuf (fp32)
    gemm_bf16<<<dim3(3072 / BN, MTOT / BM, 1), 256, GEMM_SMEM>>>(
        x2, Wall2, nullptr, q2, k2, vbuf, K1, 3072, 0, 0, 0, 1.0f, 2);

    // 3) v transpose + split
    conv_vT_kernel<<<dim3(S_LEN / 32, DMODEL / 32, BATCH), dim3(32, 8)>>>(vbuf, v2T);

    // 4) weight = scale * q @ k^T   [4][2048][2048]
    gemm_bf16<<<dim3(S_LEN / BN, S_LEN / BM, BATCH), 256, GEMM_SMEM>>>(
        q2, k2, weight, nullptr, nullptr, nullptr, K1, S_LEN,
        (long long)S_LEN * K1, (long long)S_LEN * K1, (long long)S_LEN * S_LEN,
        dist_scale, 0);

    // 5) softmax rows -> attn2 (split-A)
    softmax_kernel<<<MTOT, 256>>>(weight, attn2);

    // 6) ctx2 = attn @ v (split-A epilogue)  [2048 x 1024] per batch
    gemm_bf16<<<dim3(DMODEL / BN, S_LEN / BM, BATCH), 256, GEMM_SMEM>>>(
        attn2, v2T, ctx2, nullptr, nullptr, nullptr, K2, DMODEL,
        (long long)S_LEN * K2, (long long)DMODEL * K2, (long long)S_LEN * K1,
        1.0f, 1);

    // 7) out = ctx @ Wo^T  [8192 x 1024]
    gemm_bf16<<<dim3(DMODEL / BN, MTOT / BM, 1), 256, GEMM_SMEM>>>(
        ctx2, Wo2, out, nullptr, nullptr, nullptr, K1, DMODEL, 0, 0, 0, 1.0f, 0);
}

// round 4
// speedup vs baseline: 1.2290x; 1.1024x over previous
#include <cuda_runtime.h>
#include <cuda_bf16.h>
#include <cstdint>
#include <cstddef>

// ----------------------------------------------------------------------------
// Transformer attention, B=4, S=2048, D=1024.  Split-bf16 (K'=3K) GEMMs on
// mma.sync.m16n8k16.  128x128x64 CTA tile, 4 warps (64x64 each), 3-stage
// cp.async pipeline, 2 CTAs/SM, fused split epilogues.
// ----------------------------------------------------------------------------

#define S_LEN   2048
#define DMODEL  1024
#define BATCH   4
#define MTOT    8192
#define K1      3072
#define K2      6144

// ---------------- scratch ----------------
__device__ __nv_bfloat16 g_x2   [(size_t)MTOT  * K1];
__device__ __nv_bfloat16 g_Wall2[(size_t)3072  * K1];
__device__ __nv_bfloat16 g_Wo2  [(size_t)1024  * K1];
__device__ __nv_bfloat16 g_q2   [(size_t)MTOT  * K1];
__device__ __nv_bfloat16 g_k2   [(size_t)MTOT  * K1];
__device__ float         g_vbuf [(size_t)MTOT  * DMODEL];
__device__ __nv_bfloat16 g_v2T  [(size_t)BATCH * DMODEL * K2];
__device__ __nv_bfloat16 g_attn2[(size_t)BATCH * S_LEN  * K2];
__device__ __nv_bfloat16 g_ctx2 [(size_t)MTOT  * K1];

// ---------------- PTX helpers ----------------
__device__ __forceinline__ void mma16816(float c[4], const uint32_t a[4], const uint32_t b[2]) {
    asm volatile(
        "mma.sync.aligned.m16n8k16.row.col.f32.bf16.bf16.f32 "
        "{%0,%1,%2,%3}, {%4,%5,%6,%7}, {%8,%9}, {%0,%1,%2,%3};\n"
        : "+f"(c[0]), "+f"(c[1]), "+f"(c[2]), "+f"(c[3])
        : "r"(a[0]), "r"(a[1]), "r"(a[2]), "r"(a[3]), "r"(b[0]), "r"(b[1]));
}
__device__ __forceinline__ void ldsm_x4(uint32_t r[4], uint32_t addr) {
    asm volatile("ldmatrix.sync.aligned.m8n8.x4.shared.b16 {%0,%1,%2,%3}, [%4];\n"
                 : "=r"(r[0]), "=r"(r[1]), "=r"(r[2]), "=r"(r[3]) : "r"(addr));
}
__device__ __forceinline__ void cp16(uint32_t s, const void* g) {
    asm volatile("cp.async.cg.shared.global [%0], [%1], 16;\n" :: "r"(s), "l"(g));
}
#define CP_COMMIT()     asm volatile("cp.async.commit_group;\n" ::: "memory")
#define CP_WAIT(n)      asm volatile("cp.async.wait_group %0;\n" :: "n"(n) : "memory")

__device__ __forceinline__ uint32_t pk2(__nv_bfloat16 a, __nv_bfloat16 b) {
    return (uint32_t)__bfloat16_as_ushort(a) | ((uint32_t)__bfloat16_as_ushort(b) << 16);
}

// ---------------- GEMM: C[M,N] = op(scale * A[M,K] @ B[N,K]^T) --------------
// A,B row-major bf16, ld=K.  128x128x64 tile, 128 threads, warp tile 64x64.
// mode 0: fp32 out (ld N, *scale)
// mode 1: split-A bf16 out [hi|lo|hi], dst ld 3N
// mode 2: QKV fused: cols [0,1024) -> q2 split-A; [1024,2048) -> k2 split-B;
//         [2048,3072) -> vbuf fp32 (ld 1024)
#define BM 128
#define BN 128
#define BK 64
#define NSTG 3
#define SROW 144                          // 64 bf16 = 128B data + 16B pad
#define A_BYTES (BM * SROW)               // 18432
#define STAGE_BYTES ((BM + BN) * SROW)    // 36864
#define GEMM_SMEM (NSTG * STAGE_BYTES)    // 110592  (2 CTAs/SM)

__global__ __launch_bounds__(128, 2)
void gemm_bf16(const __nv_bfloat16* __restrict__ A,
               const __nv_bfloat16* __restrict__ B,
               void* __restrict__ Cout,
               __nv_bfloat16* __restrict__ q2,
               __nv_bfloat16* __restrict__ k2,
               float* __restrict__ vbuf,
               int K, int N,
               long long strideA, long long strideB, long long strideC,
               float scale, int mode)
{
    extern __shared__ __align__(16) unsigned char smem[];
    const uint32_t sbase = (uint32_t)__cvta_generic_to_shared(smem);

    const int b = blockIdx.z;
    A += (size_t)b * strideA;
    B += (size_t)b * strideB;

    const int bm = blockIdx.y * BM;
    const int bn = blockIdx.x * BN;
    const int tid = threadIdx.x;
    const int KT = K / BK;

    // producer mapping: 128 threads; 8 threads/row cover 128B; 16 rows/pass, 8 passes
    const int prow = tid >> 3;            // 0..15
    const int pch  = tid & 7;             // 16B chunk in 128B row slab
    const __nv_bfloat16* Ag = A + (size_t)(bm + prow) * K + pch * 8;
    const __nv_bfloat16* Bg = B + (size_t)(bn + prow) * K + pch * 8;
    const uint32_t sA = sbase + prow * SROW + pch * 16;
    const uint32_t sB = sbase + A_BYTES + prow * SROW + pch * 16;

    auto issue = [&](int kt) {
        const uint32_t st = ((kt % NSTG)) * STAGE_BYTES;
        const size_t go = (size_t)kt * BK;
        #pragma unroll
        for (int p = 0; p < 8; p++) {
            cp16(sA + st + p * 16 * SROW, Ag + go + (size_t)(p * 16) * K);
            cp16(sB + st + p * 16 * SROW, Bg + go + (size_t)(p * 16) * K);
        }
    };

    const int warp = tid >> 5;
    const int lane = tid & 31;
    const int wm = (warp & 1) * 64;
    const int wn = (warp >> 1) * 64;

    float acc[4][8][4];
    #pragma unroll
    for (int i = 0; i < 4; i++)
        #pragma unroll
        for (int j = 0; j < 8; j++)
            #pragma unroll
            for (int k = 0; k < 4; k++) acc[i][j][k] = 0.0f;

    issue(0); CP_COMMIT();
    issue(1); CP_COMMIT();

    // ldsm base offsets within a stage
    const uint32_t aOff = (wm + (lane & 15)) * SROW + (lane >> 4) * 16;
    const uint32_t bOff = A_BYTES + (wn + (lane & 7) + ((lane & 16) >> 1)) * SROW
                        + ((lane >> 3) & 1) * 16;

    for (int kt = 0; kt < KT; kt++) {
        CP_WAIT(1);
        __syncthreads();
        if (kt + 2 < KT) { issue(kt + 2); CP_COMMIT(); }

        const uint32_t st = sbase + (kt % NSTG) * STAGE_BYTES;
        #pragma unroll
        for (int ks = 0; ks < 4; ks++) {
            uint32_t ra[4][4], rb[4][4];
            #pragma unroll
            for (int mi = 0; mi < 4; mi++)
                ldsm_x4(ra[mi], st + aOff + mi * 16 * SROW + ks * 32);
            #pragma unroll
            for (int np = 0; np < 4; np++)
                ldsm_x4(rb[np], st + bOff + np * 16 * SROW + ks * 32);
            #pragma unroll
            for (int mi = 0; mi < 4; mi++)
                #pragma unroll
                for (int ni = 0; ni < 8; ni++)
                    mma16816(acc[mi][ni], ra[mi], &rb[ni >> 1][(ni & 1) * 2]);
        }
        __syncthreads();
    }

    // ---------------- epilogue ----------------
    #pragma unroll
    for (int mi = 0; mi < 4; mi++) {
        const int r0 = bm + wm + mi * 16 + (lane >> 2);
        #pragma unroll
        for (int ni = 0; ni < 8; ni++) {
            const int cl = wn + ni * 8 + (lane & 3) * 2;   // 0..127
            float v00 = acc[mi][ni][0], v01 = acc[mi][ni][1];
            float v10 = acc[mi][ni][2], v11 = acc[mi][ni][3];
            if (mode == 0) {
                float* C = (float*)Cout + (size_t)b * strideC;
                float2* p0 = (float2*)(C + (size_t)r0 * N + bn + cl);
                float2* p1 = (float2*)(C + (size_t)(r0 + 8) * N + bn + cl);
                *p0 = make_float2(v00 * scale, v01 * scale);
                *p1 = make_float2(v10 * scale, v11 * scale);
            } else if (mode == 1) {
                __nv_bfloat16* D = (__nv_bfloat16*)Cout + (size_t)b * strideC;
                #pragma unroll
                for (int rr = 0; rr < 2; rr++) {
                    float a0 = rr ? v10 : v00, a1 = rr ? v11 : v01;
                    __nv_bfloat16 h0 = __float2bfloat16(a0), h1 = __float2bfloat16(a1);
                    __nv_bfloat16 l0 = __float2bfloat16(a0 - __bfloat162float(h0));
                    __nv_bfloat16 l1 = __float2bfloat16(a1 - __bfloat162float(h1));
                    __nv_bfloat16* d = D + (size_t)(r0 + rr * 8) * (3 * N) + bn + cl;
                    *(uint32_t*)d           = pk2(h0, h1);
                    *(uint32_t*)(d + N)     = pk2(l0, l1);
                    *(uint32_t*)(d + 2 * N) = pk2(h0, h1);
                }
            } else {
                const int g = bn + cl;
                const int region = g >> 10;
                const int c = g & 1023;
                #pragma unroll
                for (int rr = 0; rr < 2; rr++) {
                    float a0 = rr ? v10 : v00, a1 = rr ? v11 : v01;
                    const size_t row = (size_t)(r0 + rr * 8);
                    if (region == 2) {
                        *(float2*)(vbuf + row * 1024 + c) = make_float2(a0, a1);
                    } else {
                        __nv_bfloat16 h0 = __float2bfloat16(a0), h1 = __float2bfloat16(a1);
                        __nv_bfloat16 l0 = __float2bfloat16(a0 - __bfloat162float(h0));
                        __nv_bfloat16 l1 = __float2bfloat16(a1 - __bfloat162float(h1));
                        if (region == 0) {            // q2: [hi | lo | hi]
                            __nv_bfloat16* d = q2 + row * 3072 + c;
                            *(uint32_t*)d            = pk2(h0, h1);
                            *(uint32_t*)(d + 1024)   = pk2(l0, l1);
                            *(uint32_t*)(d + 2048)   = pk2(h0, h1);
                        } else {                      // k2: [hi | hi | lo]
                            __nv_bfloat16* d = k2 + row * 3072 + c;
                            *(uint32_t*)d            = pk2(h0, h1);
                            *(uint32_t*)(d + 1024)   = pk2(h0, h1);
                            *(uint32_t*)(d + 2048)   = pk2(l0, l1);
                        }
                    }
                }
            }
        }
    }
}

// ---------------- vectorized split conversion ----------------
// mode 0 (A-side): [hi | lo | hi]   mode 1 (B-side): [hi | hi | lo]
__global__ void conv_split4(const float* __restrict__ src,
                            __nv_bfloat16* __restrict__ dst,
                            int n4, int K, int srcLd, int mode)
{
    int i = blockIdx.x * blockDim.x + threadIdx.x;
    if (i >= n4) return;
    int idx = i * 4;
    int row = idx / K;
    int k   = idx - row * K;
    float4 a = *(const float4*)(src + (size_t)row * srcLd + k);
    __nv_bfloat16 h0 = __float2bfloat16(a.x), h1 = __float2bfloat16(a.y);
    __nv_bfloat16 h2 = __float2bfloat16(a.z), h3 = __float2bfloat16(a.w);
    __nv_bfloat16 l0 = __float2bfloat16(a.x - __bfloat162float(h0));
    __nv_bfloat16 l1 = __float2bfloat16(a.y - __bfloat162float(h1));
    __nv_bfloat16 l2 = __float2bfloat16(a.z - __bfloat162float(h2));
    __nv_bfloat16 l3 = __float2bfloat16(a.w - __bfloat162float(h3));
    uint2 H = make_uint2(pk2(h0, h1), pk2(h2, h3));
    uint2 L = make_uint2(pk2(l0, l1), pk2(l2, l3));
    __nv_bfloat16* d = dst + (size_t)row * (3 * K) + k;
    *(uint2*)d           = H;
    *(uint2*)(d + K)     = (mode == 0) ? L : H;
    *(uint2*)(d + 2 * K) = (mode == 0) ? H : L;
}

// V transpose + split (B-side):  v2T[b][j][t | 2048+t | 4096+t]
__global__ void conv_vT_kernel(const float* __restrict__ vbuf,
                               __nv_bfloat16* __restrict__ v2T)
{
    __shared__ float tile[32][33];
    const int b  = blockIdx.z;
    const int t0 = blockIdx.x * 32;
    const int j0 = blockIdx.y * 32;
    const int tx = threadIdx.x, ty = threadIdx.y;   // 32 x 8

    #pragma unroll
    for (int i = 0; i < 32; i += 8)
        tile[ty + i][tx] = vbuf[((size_t)(b * S_LEN + t0 + ty + i)) * DMODEL + j0 + tx];
    __syncthreads();

    #pragma unroll
    for (int i = 0; i < 32; i += 8) {
        int j = j0 + ty + i;
        int t = t0 + tx;
        float a = tile[tx][ty + i];
        __nv_bfloat16 hi = __float2bfloat16(a);
        __nv_bfloat16 lo = __float2bfloat16(a - __bfloat162float(hi));
        __nv_bfloat16* d = v2T + ((size_t)b * DMODEL + j) * K2 + t;
        d[0] = hi; d[S_LEN] = hi; d[2 * S_LEN] = lo;
    }
}

// softmax over rows of dist (already scaled); write attn split (A-side)
__global__ void softmax_kernel(const float* __restrict__ dist,
                               __nv_bfloat16* __restrict__ attn2)
{
    const int row = blockIdx.x;
    const int tid = threadIdx.x;                  // 256
    const float4* d4 = (const float4*)(dist + (size_t)row * S_LEN) + tid * 2;
    float4 v0 = d4[0], v1 = d4[1];
    float v[8] = {v0.x, v0.y, v0.z, v0.w, v1.x, v1.y, v1.z, v1.w};

    float m = v[0];
    #pragma unroll
    for (int i = 1; i < 8; i++) m = fmaxf(m, v[i]);
    __shared__ float red[8];
    #pragma unroll
    for (int o = 16; o; o >>= 1) m = fmaxf(m, __shfl_xor_sync(0xffffffffu, m, o));
    if ((tid & 31) == 0) red[tid >> 5] = m;
    __syncthreads();
    m = red[0];
    #pragma unroll
    for (int i = 1; i < 8; i++) m = fmaxf(m, red[i]);
    __syncthreads();

    float s = 0.0f;
    #pragma unroll
    for (int i = 0; i < 8; i++) { v[i] = __expf(v[i] - m); s += v[i]; }
    #pragma unroll
    for (int o = 16; o; o >>= 1) s += __shfl_xor_sync(0xffffffffu, s, o);
    if ((tid & 31) == 0) red[tid >> 5] = s;
    __syncthreads();
    float tot = 0.0f;
    #pragma unroll
    for (int i = 0; i < 8; i++) tot += red[i];
    const float inv = 1.0f / tot;

    uint32_t H[4], L[4];
    #pragma unroll
    for (int i = 0; i < 4; i++) {
        float p0 = v[2 * i] * inv, p1 = v[2 * i + 1] * inv;
        __nv_bfloat16 h0 = __float2bfloat16(p0), h1 = __float2bfloat16(p1);
        __nv_bfloat16 l0 = __float2bfloat16(p0 - __bfloat162float(h0));
        __nv_bfloat16 l1 = __float2bfloat16(p1 - __bfloat162float(h1));
        H[i] = pk2(h0, h1); L[i] = pk2(l0, l1);
    }
    __nv_bfloat16* a2 = attn2 + (size_t)row * K2 + tid * 8;
    *(uint4*)(a2)             = make_uint4(H[0], H[1], H[2], H[3]);
    *(uint4*)(a2 + S_LEN)     = make_uint4(L[0], L[1], L[2], L[3]);
    *(uint4*)(a2 + 2 * S_LEN) = make_uint4(H[0], H[1], H[2], H[3]);
}

// ---------------- launch ----------------
extern "C" void kernel_launch(void* const* d_in, const int* in_sizes, int n_in,
                              void* d_out, int out_size)
{
    (void)in_sizes; (void)n_in; (void)out_size;
    const float* x  = (const float*)d_in[0];
    const float* Wq = (const float*)d_in[1];
    const float* Wk = (const float*)d_in[2];
    const float* Wv = (const float*)d_in[3];
    const float* Wo = (const float*)d_in[4];

    float* out    = (float*)d_out;                       // [4,2048,1024]
    float* weight = out + (size_t)MTOT * DMODEL;         // [4,2048,2048]

    void *p_x2, *p_Wall2, *p_Wo2, *p_q2, *p_k2, *p_vbuf, *p_v2T, *p_attn2, *p_ctx2;
    cudaGetSymbolAddress(&p_x2,    g_x2);
    cudaGetSymbolAddress(&p_Wall2, g_Wall2);
    cudaGetSymbolAddress(&p_Wo2,   g_Wo2);
    cudaGetSymbolAddress(&p_q2,    g_q2);
    cudaGetSymbolAddress(&p_k2,    g_k2);
    cudaGetSymbolAddress(&p_vbuf,  g_vbuf);
    cudaGetSymbolAddress(&p_v2T,   g_v2T);
    cudaGetSymbolAddress(&p_attn2, g_attn2);
    cudaGetSymbolAddress(&p_ctx2,  g_ctx2);

    __nv_bfloat16* x2    = (__nv_bfloat16*)p_x2;
    __nv_bfloat16* Wall2 = (__nv_bfloat16*)p_Wall2;
    __nv_bfloat16* Wo2   = (__nv_bfloat16*)p_Wo2;
    __nv_bfloat16* q2    = (__nv_bfloat16*)p_q2;
    __nv_bfloat16* k2    = (__nv_bfloat16*)p_k2;
    float*         vbuf  = (float*)p_vbuf;
    __nv_bfloat16* v2T   = (__nv_bfloat16*)p_v2T;
    __nv_bfloat16* attn2 = (__nv_bfloat16*)p_attn2;
    __nv_bfloat16* ctx2  = (__nv_bfloat16*)p_ctx2;

    cudaFuncSetAttribute(gemm_bf16, cudaFuncAttributeMaxDynamicSharedMemorySize, GEMM_SMEM);

    const int CT = 256;
    const float dist_scale = 0.044194173824159223f;   // (1024/2)^-0.5

    // 1) split-convert inputs
    conv_split4<<<(MTOT * DMODEL / 4 + CT - 1) / CT, CT>>>(x, x2, MTOT * DMODEL / 4, DMODEL, DMODEL, 0);
    conv_split4<<<(1024 * 1024 / 4 + CT - 1) / CT, CT>>>(Wq, Wall2,                     1024 * 1024 / 4, 1024, 1024, 1);
    conv_split4<<<(1024 * 1024 / 4 + CT - 1) / CT, CT>>>(Wk, Wall2 + (size_t)1024 * K1, 1024 * 1024 / 4, 1024, 1024, 1);
    conv_split4<<<(1024 * 1024 / 4 + CT - 1) / CT, CT>>>(Wv, Wall2 + (size_t)2048 * K1, 1024 * 1024 / 4, 1024, 1024, 1);
    conv_split4<<<(1024 * 1024 / 4 + CT - 1) / CT, CT>>>(Wo, Wo2,                       1024 * 1024 / 4, 1024, 1024, 1);

    // 2) QKV fused: x2 @ Wall2^T -> q2 (split-A), k2 (split-B), vbuf (fp32)
    gemm_bf16<<<dim3(3072 / BN, MTOT / BM, 1), 128, GEMM_SMEM>>>(
        x2, Wall2, nullptr, q2, k2, vbuf, K1, 3072, 0, 0, 0, 1.0f, 2);

    // 3) v transpose + split
    conv_vT_kernel<<<dim3(S_LEN / 32, DMODEL / 32, BATCH), dim3(32, 8)>>>(vbuf, v2T);

    // 4) weight = scale * q @ k^T   [4][2048][2048]
    gemm_bf16<<<dim3(S_LEN / BN, S_LEN / BM, BATCH), 128, GEMM_SMEM>>>(
        q2, k2, weight, nullptr, nullptr, nullptr, K1, S_LEN,
        (long long)S_LEN * K1, (long long)S_LEN * K1, (long long)S_LEN * S_LEN,
        dist_scale, 0);

    // 5) softmax rows -> attn2 (split-A)
    softmax_kernel<<<MTOT, 256>>>(weight, attn2);

    // 6) ctx2 = attn @ v (split-A epilogue)  [2048 x 1024] per batch
    gemm_bf16<<<dim3(DMODEL / BN, S_LEN / BM, BATCH), 128, GEMM_SMEM>>>(
        attn2, v2T, ctx2, nullptr, nullptr, nullptr, K2, DMODEL,
        (long long)S_LEN * K2, (long long)DMODEL * K2, (long long)S_LEN * K1,
        1.0f, 1);

    // 7) out = ctx @ Wo^T  [8192 x 1024]
    gemm_bf16<<<dim3(DMODEL / BN, MTOT / BM, 1), 128, GEMM_SMEM>>>(
        ctx2, Wo2, out, nullptr, nullptr, nullptr, K1, DMODEL, 0, 0, 0, 1.0f, 0);
}

// round 5
// speedup vs baseline: 1.2856x; 1.0461x over previous
#include <cuda_runtime.h>
#include <cuda_bf16.h>
#include <cstdint>
#include <cstddef>

// ----------------------------------------------------------------------------
// Transformer attention, B=4, S=2048, D=1024.  Split-bf16 GEMMs (logical
// K'=3K: A=[hi|lo|hi], B=[hi|hi|lo]) with DEDUPED physical [hi|lo] storage;
// per-stage producer remap supplies the duplicate segment.
// mma.sync.m16n8k16, 128x128x64 tile, 4 warps (64x64), 3-stage cp.async,
// one barrier per stage, 2 CTAs/SM, fused split epilogues.
// ----------------------------------------------------------------------------

#define S_LEN   2048
#define DMODEL  1024
#define BATCH   4
#define MTOT    8192
#define K1      3072            // logical (3 * 1024)
#define K2      6144            // logical (3 * 2048)

// ---------------- scratch (physical [hi|lo] layouts, ld = 2*K/3) ------------
__device__ __nv_bfloat16 g_x2   [(size_t)MTOT  * 2048];
__device__ __nv_bfloat16 g_Wall2[(size_t)3072  * 2048];
__device__ __nv_bfloat16 g_Wo2  [(size_t)1024  * 2048];
__device__ __nv_bfloat16 g_q2   [(size_t)MTOT  * 2048];
__device__ __nv_bfloat16 g_k2   [(size_t)MTOT  * 2048];
__device__ float         g_vbuf [(size_t)MTOT  * DMODEL];
__device__ __nv_bfloat16 g_v2T  [(size_t)BATCH * DMODEL * 4096];
__device__ __nv_bfloat16 g_attn2[(size_t)BATCH * S_LEN  * 4096];
__device__ __nv_bfloat16 g_ctx2 [(size_t)MTOT  * 2048];

// ---------------- PTX helpers ----------------
__device__ __forceinline__ void mma16816(float c[4], const uint32_t a[4], const uint32_t b[2]) {
    asm volatile(
        "mma.sync.aligned.m16n8k16.row.col.f32.bf16.bf16.f32 "
        "{%0,%1,%2,%3}, {%4,%5,%6,%7}, {%8,%9}, {%0,%1,%2,%3};\n"
        : "+f"(c[0]), "+f"(c[1]), "+f"(c[2]), "+f"(c[3])
        : "r"(a[0]), "r"(a[1]), "r"(a[2]), "r"(a[3]), "r"(b[0]), "r"(b[1]));
}
__device__ __forceinline__ void ldsm_x4(uint32_t r[4], uint32_t addr) {
    asm volatile("ldmatrix.sync.aligned.m8n8.x4.shared.b16 {%0,%1,%2,%3}, [%4];\n"
                 : "=r"(r[0]), "=r"(r[1]), "=r"(r[2]), "=r"(r[3]) : "r"(addr));
}
__device__ __forceinline__ void cp16(uint32_t s, const void* g) {
    asm volatile("cp.async.cg.shared.global [%0], [%1], 16;\n" :: "r"(s), "l"(g));
}
#define CP_COMMIT()     asm volatile("cp.async.commit_group;\n" ::: "memory")
#define CP_WAIT(n)      asm volatile("cp.async.wait_group %0;\n" :: "n"(n) : "memory")

__device__ __forceinline__ uint32_t pk2(__nv_bfloat16 a, __nv_bfloat16 b) {
    return (uint32_t)__bfloat16_as_ushort(a) | ((uint32_t)__bfloat16_as_ushort(b) << 16);
}

// ---------------- GEMM: C[M,N] = op(scale * A'[M,K] @ B'[N,K]^T) ------------
// Logical K = 3*Kthird.  Physical A,B are [hi|lo], ld = 2*Kthird.
// Stage column remap: A: o>=2*Kthird -> o-2*Kthird ; B: o>=Kthird -> o-Kthird.
// mode 0: fp32 out (ld N, *scale)
// mode 1: dedup split out (ctx2): hi at c, lo at c+1024; ld 2048
// mode 2: QKV fused: cols [0,1024)->q2, [1024,2048)->k2 (both dedup split,
//         ld 2048); [2048,3072)->vbuf fp32 (ld 1024)
#define BM 128
#define BN 128
#define BK 64
#define NSTG 3
#define SROW 144                          // 64 bf16 = 128B data + 16B pad
#define A_BYTES (BM * SROW)               // 18432
#define STAGE_BYTES ((BM + BN) * SROW)    // 36864
#define GEMM_SMEM (NSTG * STAGE_BYTES)    // 110592  (2 CTAs/SM)

__global__ __launch_bounds__(128, 2)
void gemm_bf16(const __nv_bfloat16* __restrict__ A,
               const __nv_bfloat16* __restrict__ B,
               void* __restrict__ Cout,
               __nv_bfloat16* __restrict__ q2,
               __nv_bfloat16* __restrict__ k2,
               float* __restrict__ vbuf,
               int K, int N,
               long long strideA, long long strideB, long long strideC,
               float scale, int mode)
{
    extern __shared__ __align__(16) unsigned char smem[];
    const uint32_t sbase = (uint32_t)__cvta_generic_to_shared(smem);

    const int Kthird = K / 3;
    const int ldAB   = 2 * Kthird;

    const int b = blockIdx.z;
    A += (size_t)b * strideA;
    B += (size_t)b * strideB;

    const int bm = blockIdx.y * BM;
    const int bn = blockIdx.x * BN;
    const int tid = threadIdx.x;
    const int KT = K / BK;

    // producer mapping: 8 threads/row (128B), 16 rows/pass, 8 passes
    const int prow = tid >> 3;            // 0..15
    const int pch  = tid & 7;
    const __nv_bfloat16* Ag = A + (size_t)(bm + prow) * ldAB + pch * 8;
    const __nv_bfloat16* Bg = B + (size_t)(bn + prow) * ldAB + pch * 8;
    const uint32_t sA = sbase + prow * SROW + pch * 16;
    const uint32_t sB = sbase + A_BYTES + prow * SROW + pch * 16;

    auto issue = [&](int kt) {
        const uint32_t st = (kt % NSTG) * STAGE_BYTES;
        const int o  = kt * BK;
        const int oa = (o >= 2 * Kthird) ? o - 2 * Kthird : o;
        const int ob = (o >= Kthird)     ? o - Kthird     : o;
        #pragma unroll
        for (int p = 0; p < 8; p++) {
            cp16(sA + st + p * 16 * SROW, Ag + oa + (size_t)(p * 16) * ldAB);
            cp16(sB + st + p * 16 * SROW, Bg + ob + (size_t)(p * 16) * ldAB);
        }
    };

    const int warp = tid >> 5;
    const int lane = tid & 31;
    const int wm = (warp & 1) * 64;
    const int wn = (warp >> 1) * 64;

    float acc[4][8][4];
    #pragma unroll
    for (int i = 0; i < 4; i++)
        #pragma unroll
        for (int j = 0; j < 8; j++)
            #pragma unroll
            for (int k = 0; k < 4; k++) acc[i][j][k] = 0.0f;

    issue(0); CP_COMMIT();
    issue(1); CP_COMMIT();

    const uint32_t aOff = (wm + (lane & 15)) * SROW + (lane >> 4) * 16;
    const uint32_t bOff = A_BYTES + (wn + (lane & 7) + ((lane & 16) >> 1)) * SROW
                        + ((lane >> 3) & 1) * 16;

    for (int kt = 0; kt < KT; kt++) {
        CP_WAIT(1);                 // stage kt arrived (empty groups keep order)
        __syncthreads();            // also: all warps done with stage kt-1
        if (kt + 2 < KT) issue(kt + 2);
        CP_COMMIT();                // unconditional: keeps wait_group counting safe

        const uint32_t st = sbase + (kt % NSTG) * STAGE_BYTES;
        #pragma unroll
        for (int ks = 0; ks < 4; ks++) {
            uint32_t ra[4][4], rb[4][4];
            #pragma unroll
            for (int mi = 0; mi < 4; mi++)
                ldsm_x4(ra[mi], st + aOff + mi * 16 * SROW + ks * 32);
            #pragma unroll
            for (int np = 0; np < 4; np++)
                ldsm_x4(rb[np], st + bOff + np * 16 * SROW + ks * 32);
            #pragma unroll
            for (int mi = 0; mi < 4; mi++)
                #pragma unroll
                for (int ni = 0; ni < 8; ni++)
                    mma16816(acc[mi][ni], ra[mi], &rb[ni >> 1][(ni & 1) * 2]);
        }
    }

    // ---------------- epilogue ----------------
    #pragma unroll
    for (int mi = 0; mi < 4; mi++) {
        const int r0 = bm + wm + mi * 16 + (lane >> 2);
        #pragma unroll
        for (int ni = 0; ni < 8; ni++) {
            const int cl = wn + ni * 8 + (lane & 3) * 2;
            float v00 = acc[mi][ni][0], v01 = acc[mi][ni][1];
            float v10 = acc[mi][ni][2], v11 = acc[mi][ni][3];
            if (mode == 0) {
                float* C = (float*)Cout + (size_t)b * strideC;
                float2* p0 = (float2*)(C + (size_t)r0 * N + bn + cl);
                float2* p1 = (float2*)(C + (size_t)(r0 + 8) * N + bn + cl);
                *p0 = make_float2(v00 * scale, v01 * scale);
                *p1 = make_float2(v10 * scale, v11 * scale);
            } else if (mode == 1) {
                __nv_bfloat16* D = (__nv_bfloat16*)Cout + (size_t)b * strideC;
                #pragma unroll
                for (int rr = 0; rr < 2; rr++) {
                    float a0 = rr ? v10 : v00, a1 = rr ? v11 : v01;
                    __nv_bfloat16 h0 = __float2bfloat16(a0), h1 = __float2bfloat16(a1);
                    __nv_bfloat16 l0 = __float2bfloat16(a0 - __bfloat162float(h0));
                    __nv_bfloat16 l1 = __float2bfloat16(a1 - __bfloat162float(h1));
                    __nv_bfloat16* d = D + (size_t)(r0 + rr * 8) * 2048 + bn + cl;
                    *(uint32_t*)d          = pk2(h0, h1);
                    *(uint32_t*)(d + 1024) = pk2(l0, l1);
                }
            } else {
                const int g = bn + cl;
                const int region = g >> 10;
                const int c = g & 1023;
                #pragma unroll
                for (int rr = 0; rr < 2; rr++) {
                    float a0 = rr ? v10 : v00, a1 = rr ? v11 : v01;
                    const size_t row = (size_t)(r0 + rr * 8);
                    if (region == 2) {
                        *(float2*)(vbuf + row * 1024 + c) = make_float2(a0, a1);
                    } else {
                        __nv_bfloat16 h0 = __float2bfloat16(a0), h1 = __float2bfloat16(a1);
                        __nv_bfloat16 l0 = __float2bfloat16(a0 - __bfloat162float(h0));
                        __nv_bfloat16 l1 = __float2bfloat16(a1 - __bfloat162float(h1));
                        __nv_bfloat16* base = (region == 0) ? q2 : k2;
                        __nv_bfloat16* d = base + row * 2048 + c;
                        *(uint32_t*)d          = pk2(h0, h1);
                        *(uint32_t*)(d + 1024) = pk2(l0, l1);
                    }
                }
            }
        }
    }
}

// ---------------- conversions (dedup [hi|lo] layout) ----------------
__device__ __forceinline__ void split8_store(const float* s, __nv_bfloat16* d, int K) {
    float4 a = *(const float4*)s;
    float4 b = *(const float4*)(s + 4);
    __nv_bfloat16 h[8], l[8];
    float v[8] = {a.x, a.y, a.z, a.w, b.x, b.y, b.z, b.w};
    #pragma unroll
    for (int i = 0; i < 8; i++) {
        h[i] = __float2bfloat16(v[i]);
        l[i] = __float2bfloat16(v[i] - __bfloat162float(h[i]));
    }
    *(uint4*)d       = make_uint4(pk2(h[0], h[1]), pk2(h[2], h[3]), pk2(h[4], h[5]), pk2(h[6], h[7]));
    *(uint4*)(d + K) = make_uint4(pk2(l[0], l[1]), pk2(l[2], l[3]), pk2(l[4], l[5]), pk2(l[6], l[7]));
}

__global__ void conv_x_kernel(const float* __restrict__ x, __nv_bfloat16* __restrict__ x2)
{
    int i = blockIdx.x * blockDim.x + threadIdx.x;          // 1M threads
    int idx = i * 8;
    int row = idx >> 10;
    int k   = idx & 1023;
    split8_store(x + (size_t)row * 1024 + k, x2 + (size_t)row * 2048 + k, 1024);
}

__global__ void conv_w_kernel(const float* __restrict__ Wq, const float* __restrict__ Wk,
                              const float* __restrict__ Wv, const float* __restrict__ Wo,
                              __nv_bfloat16* __restrict__ Wall2, __nv_bfloat16* __restrict__ Wo2)
{
    const int slice = blockIdx.y;
    const float* src = (slice == 0) ? Wq : (slice == 1) ? Wk : (slice == 2) ? Wv : Wo;
    __nv_bfloat16* dst = (slice < 3) ? Wall2 + (size_t)slice * 1024 * 2048 : Wo2;
    int i = blockIdx.x * blockDim.x + threadIdx.x;          // 128K threads
    int idx = i * 8;
    int row = idx >> 10;
    int k   = idx & 1023;
    split8_store(src + (size_t)row * 1024 + k, dst + (size_t)row * 2048 + k, 1024);
}

// V transpose + split:  v2T[b][j] = [hi(t) | lo(t)+2048], ld 4096
__global__ void conv_vT_kernel(const float* __restrict__ vbuf,
                               __nv_bfloat16* __restrict__ v2T)
{
    __shared__ float tile[32][33];
    const int b  = blockIdx.z;
    const int t0 = blockIdx.x * 32;
    const int j0 = blockIdx.y * 32;
    const int tx = threadIdx.x, ty = threadIdx.y;   // 32 x 8

    #pragma unroll
    for (int i = 0; i < 32; i += 8)
        tile[ty + i][tx] = vbuf[((size_t)(b * S_LEN + t0 + ty + i)) * DMODEL + j0 + tx];
    __syncthreads();

    #pragma unroll
    for (int i = 0; i < 32; i += 8) {
        int j = j0 + ty + i;
        int t = t0 + tx;
        float a = tile[tx][ty + i];
        __nv_bfloat16 hi = __float2bfloat16(a);
        __nv_bfloat16 lo = __float2bfloat16(a - __bfloat162float(hi));
        __nv_bfloat16* d = v2T + ((size_t)b * DMODEL + j) * 4096 + t;
        d[0] = hi; d[2048] = lo;
    }
}

// softmax over rows; write attn2 dedup [hi|lo], ld 4096
__global__ void softmax_kernel(const float* __restrict__ dist,
                               __nv_bfloat16* __restrict__ attn2)
{
    const int row = blockIdx.x;
    const int tid = threadIdx.x;                  // 256
    const float4* d4 = (const float4*)(dist + (size_t)row * S_LEN) + tid * 2;
    float4 v0 = d4[0], v1 = d4[1];
    float v[8] = {v0.x, v0.y, v0.z, v0.w, v1.x, v1.y, v1.z, v1.w};

    float m = v[0];
    #pragma unroll
    for (int i = 1; i < 8; i++) m = fmaxf(m, v[i]);
    __shared__ float red[8];
    #pragma unroll
    for (int o = 16; o; o >>= 1) m = fmaxf(m, __shfl_xor_sync(0xffffffffu, m, o));
    if ((tid & 31) == 0) red[tid >> 5] = m;
    __syncthreads();
    m = red[0];
    #pragma unroll
    for (int i = 1; i < 8; i++) m = fmaxf(m, red[i]);
    __syncthreads();

    float s = 0.0f;
    #pragma unroll
    for (int i = 0; i < 8; i++) { v[i] = __expf(v[i] - m); s += v[i]; }
    #pragma unroll
    for (int o = 16; o; o >>= 1) s += __shfl_xor_sync(0xffffffffu, s, o);
    if ((tid & 31) == 0) red[tid >> 5] = s;
    __syncthreads();
    float tot = 0.0f;
    #pragma unroll
    for (int i = 0; i < 8; i++) tot += red[i];
    const float inv = 1.0f / tot;

    uint32_t H[4], L[4];
    #pragma unroll
    for (int i = 0; i < 4; i++) {
        float p0 = v[2 * i] * inv, p1 = v[2 * i + 1] * inv;
        __nv_bfloat16 h0 = __float2bfloat16(p0), h1 = __float2bfloat16(p1);
        __nv_bfloat16 l0 = __float2bfloat16(p0 - __bfloat162float(h0));
        __nv_bfloat16 l1 = __float2bfloat16(p1 - __bfloat162float(h1));
        H[i] = pk2(h0, h1); L[i] = pk2(l0, l1);
    }
    __nv_bfloat16* a2 = attn2 + (size_t)row * 4096 + tid * 8;
    *(uint4*)(a2)        = make_uint4(H[0], H[1], H[2], H[3]);
    *(uint4*)(a2 + 2048) = make_uint4(L[0], L[1], L[2], L[3]);
}

// ---------------- launch ----------------
extern "C" void kernel_launch(void* const* d_in, const int* in_sizes, int n_in,
                              void* d_out, int out_size)
{
    (void)in_sizes; (void)n_in; (void)out_size;
    const float* x  = (const float*)d_in[0];
    const float* Wq = (const float*)d_in[1];
    const float* Wk = (const float*)d_in[2];
    const float* Wv = (const float*)d_in[3];
    const float* Wo = (const float*)d_in[4];

    float* out    = (float*)d_out;                       // [4,2048,1024]
    float* weight = out + (size_t)MTOT * DMODEL;         // [4,2048,2048]

    void *p_x2, *p_Wall2, *p_Wo2, *p_q2, *p_k2, *p_vbuf, *p_v2T, *p_attn2, *p_ctx2;
    cudaGetSymbolAddress(&p_x2,    g_x2);
    cudaGetSymbolAddress(&p_Wall2, g_Wall2);
    cudaGetSymbolAddress(&p_Wo2,   g_Wo2);
    cudaGetSymbolAddress(&p_q2,    g_q2);
    cudaGetSymbolAddress(&p_k2,    g_k2);
    cudaGetSymbolAddress(&p_vbuf,  g_vbuf);
    cudaGetSymbolAddress(&p_v2T,   g_v2T);
    cudaGetSymbolAddress(&p_attn2, g_attn2);
    cudaGetSymbolAddress(&p_ctx2,  g_ctx2);

    __nv_bfloat16* x2    = (__nv_bfloat16*)p_x2;
    __nv_bfloat16* Wall2 = (__nv_bfloat16*)p_Wall2;
    __nv_bfloat16* Wo2   = (__nv_bfloat16*)p_Wo2;
    __nv_bfloat16* q2    = (__nv_bfloat16*)p_q2;
    __nv_bfloat16* k2    = (__nv_bfloat16*)p_k2;
    float*         vbuf  = (float*)p_vbuf;
    __nv_bfloat16* v2T   = (__nv_bfloat16*)p_v2T;
    __nv_bfloat16* attn2 = (__nv_bfloat16*)p_attn2;
    __nv_bfloat16* ctx2  = (__nv_bfloat16*)p_ctx2;

    cudaFuncSetAttribute(gemm_bf16, cudaFuncAttributeMaxDynamicSharedMemorySize, GEMM_SMEM);

    const float dist_scale = 0.044194173824159223f;   // (1024/2)^-0.5

    // 1) split-convert inputs (dedup layouts)
    conv_x_kernel<<<MTOT * DMODEL / 8 / 256, 256>>>(x, x2);
    conv_w_kernel<<<dim3(1024 * 1024 / 8 / 256, 4), 256>>>(Wq, Wk, Wv, Wo, Wall2, Wo2);

    // 2) QKV fused: x2 @ Wall2^T -> q2, k2 (dedup split), vbuf (fp32)
    gemm_bf16<<<dim3(3072 / BN, MTOT / BM, 1), 128, GEMM_SMEM>>>(
        x2, Wall2, nullptr, q2, k2, vbuf, K1, 3072, 0, 0, 0, 1.0f, 2);

    // 3) v transpose + split
    conv_vT_kernel<<<dim3(S_LEN / 32, DMODEL / 32, BATCH), dim3(32, 8)>>>(vbuf, v2T);

    // 4) weight = scale * q @ k^T   [4][2048][2048]
    gemm_bf16<<<dim3(S_LEN / BN, S_LEN / BM, BATCH), 128, GEMM_SMEM>>>(
        q2, k2, weight, nullptr, nullptr, nullptr, K1, S_LEN,
        (long long)S_LEN * 2048, (long long)S_LEN * 2048, (long long)S_LEN * S_LEN,
        dist_scale, 0);

    // 5) softmax rows -> attn2 (dedup split)
    softmax_kernel<<<MTOT, 256>>>(weight, attn2);

    // 6) ctx2 = attn @ v -> dedup split   [2048 x 1024] per batch
    gemm_bf16<<<dim3(DMODEL / BN, S_LEN / BM, BATCH), 128, GEMM_SMEM>>>(
        attn2, v2T, ctx2, nullptr, nullptr, nullptr, K2, DMODEL,
        (long long)S_LEN * 4096, (long long)DMODEL * 4096, (long long)S_LEN * 2048,
        1.0f, 1);

    // 7) out = ctx @ Wo^T  [8192 x 1024]
    gemm_bf16<<<dim3(DMODEL / BN, MTOT / BM, 1), 128, GEMM_SMEM>>>(
        ctx2, Wo2, out, nullptr, nullptr, nullptr, K1, DMODEL, 0, 0, 0, 1.0f, 0);
}

// round 6
// speedup vs baseline: 1.3688x; 1.0647x over previous
#include <cuda_runtime.h>
#include <cuda_bf16.h>
#include <cstdint>
#include <cstddef>

// ----------------------------------------------------------------------------
// Transformer attention, B=4, S=2048, D=1024.  Split-bf16 GEMMs (logical
// K'=3K: A=[hi|lo|hi], B=[hi|hi|lo]) with deduped physical [hi|lo] storage.
// mma.sync.m16n8k16, 128x128x64 tile, 4 warps (64x64), 3-stage cp.async,
// register-fragment double buffering, 2 CTAs/SM, fused split epilogues.
// ----------------------------------------------------------------------------

#define S_LEN   2048
#define DMODEL  1024
#define BATCH   4
#define MTOT    8192
#define K1      3072            // logical (3 * 1024)
#define K2      6144            // logical (3 * 2048)

// ---------------- scratch (physical [hi|lo] layouts, ld = 2*K/3) ------------
__device__ __nv_bfloat16 g_x2   [(size_t)MTOT  * 2048];
__device__ __nv_bfloat16 g_Wall2[(size_t)3072  * 2048];
__device__ __nv_bfloat16 g_Wo2  [(size_t)1024  * 2048];
__device__ __nv_bfloat16 g_q2   [(size_t)MTOT  * 2048];
__device__ __nv_bfloat16 g_k2   [(size_t)MTOT  * 2048];
__device__ float         g_vbuf [(size_t)MTOT  * DMODEL];
__device__ __nv_bfloat16 g_v2T  [(size_t)BATCH * DMODEL * 4096];
__device__ __nv_bfloat16 g_attn2[(size_t)BATCH * S_LEN  * 4096];
__device__ __nv_bfloat16 g_ctx2 [(size_t)MTOT  * 2048];

// ---------------- PTX helpers ----------------
__device__ __forceinline__ void mma16816(float c[4], const uint32_t a[4], const uint32_t b[2]) {
    asm volatile(
        "mma.sync.aligned.m16n8k16.row.col.f32.bf16.bf16.f32 "
        "{%0,%1,%2,%3}, {%4,%5,%6,%7}, {%8,%9}, {%0,%1,%2,%3};\n"
        : "+f"(c[0]), "+f"(c[1]), "+f"(c[2]), "+f"(c[3])
        : "r"(a[0]), "r"(a[1]), "r"(a[2]), "r"(a[3]), "r"(b[0]), "r"(b[1]));
}
__device__ __forceinline__ void ldsm_x4(uint32_t r[4], uint32_t addr) {
    asm volatile("ldmatrix.sync.aligned.m8n8.x4.shared.b16 {%0,%1,%2,%3}, [%4];\n"
                 : "=r"(r[0]), "=r"(r[1]), "=r"(r[2]), "=r"(r[3]) : "r"(addr));
}
__device__ __forceinline__ void cp16(uint32_t s, const void* g) {
    asm volatile("cp.async.cg.shared.global [%0], [%1], 16;\n" :: "r"(s), "l"(g));
}
#define CP_COMMIT()     asm volatile("cp.async.commit_group;\n" ::: "memory")
#define CP_WAIT(n)      asm volatile("cp.async.wait_group %0;\n" :: "n"(n) : "memory")

__device__ __forceinline__ uint32_t pk2(__nv_bfloat16 a, __nv_bfloat16 b) {
    return (uint32_t)__bfloat16_as_ushort(a) | ((uint32_t)__bfloat16_as_ushort(b) << 16);
}

// ---------------- GEMM: C[M,N] = op(scale * A'[M,K] @ B'[N,K]^T) ------------
// Logical K = 3*Kthird.  Physical A,B are [hi|lo], ld = 2*Kthird.
// Stage column remap: A: o>=2*Kthird -> o-2*Kthird ; B: o>=Kthird -> o-Kthird.
// mode 0: fp32 out (ld N, *scale)
// mode 1: dedup split out (ctx2): hi at c, lo at c+1024; ld 2048
// mode 2: QKV fused: cols [0,1024)->q2, [1024,2048)->k2 (dedup split, ld 2048);
//         [2048,3072)->vbuf fp32 (ld 1024)
#define BM 128
#define BN 128
#define BK 64
#define NSTG 3
#define SROW 144                          // 64 bf16 = 128B data + 16B pad
#define A_BYTES (BM * SROW)               // 18432
#define STAGE_BYTES ((BM + BN) * SROW)    // 36864
#define GEMM_SMEM (NSTG * STAGE_BYTES)    // 110592  (2 CTAs/SM)

__device__ __forceinline__ void load_frags(uint32_t st, uint32_t aOff, uint32_t bOff,
                                           int ks, uint32_t ra[4][4], uint32_t rb[4][4]) {
    #pragma unroll
    for (int mi = 0; mi < 4; mi++)
        ldsm_x4(ra[mi], st + aOff + mi * 16 * SROW + ks * 32);
    #pragma unroll
    for (int np = 0; np < 4; np++)
        ldsm_x4(rb[np], st + bOff + np * 16 * SROW + ks * 32);
}

__global__ __launch_bounds__(128, 2)
void gemm_bf16(const __nv_bfloat16* __restrict__ A,
               const __nv_bfloat16* __restrict__ B,
               void* __restrict__ Cout,
               __nv_bfloat16* __restrict__ q2,
               __nv_bfloat16* __restrict__ k2,
               float* __restrict__ vbuf,
               int K, int N,
               long long strideA, long long strideB, long long strideC,
               float scale, int mode)
{
    extern __shared__ __align__(16) unsigned char smem[];
    const uint32_t sbase = (uint32_t)__cvta_generic_to_shared(smem);

    const int Kthird = K / 3;
    const int ldAB   = 2 * Kthird;

    const int b = blockIdx.z;
    A += (size_t)b * strideA;
    B += (size_t)b * strideB;

    const int bm = blockIdx.y * BM;
    const int bn = blockIdx.x * BN;
    const int tid = threadIdx.x;
    const int KT = K / BK;

    // producer mapping: 8 threads/row (128B), 16 rows/pass, 8 passes
    const int prow = tid >> 3;            // 0..15
    const int pch  = tid & 7;
    const __nv_bfloat16* Ag = A + (size_t)(bm + prow) * ldAB + pch * 8;
    const __nv_bfloat16* Bg = B + (size_t)(bn + prow) * ldAB + pch * 8;
    const uint32_t sA = sbase + prow * SROW + pch * 16;
    const uint32_t sB = sbase + A_BYTES + prow * SROW + pch * 16;

    auto issue = [&](int kt, int stg) {
        const uint32_t st = stg * STAGE_BYTES;
        const int o  = kt * BK;
        const int oa = (o >= 2 * Kthird) ? o - 2 * Kthird : o;
        const int ob = (o >= Kthird)     ? o - Kthird     : o;
        #pragma unroll
        for (int p = 0; p < 8; p++) {
            cp16(sA + st + p * 16 * SROW, Ag + oa + (size_t)(p * 16) * ldAB);
            cp16(sB + st + p * 16 * SROW, Bg + ob + (size_t)(p * 16) * ldAB);
        }
    };

    const int warp = tid >> 5;
    const int lane = tid & 31;
    const int wm = (warp & 1) * 64;
    const int wn = (warp >> 1) * 64;

    float acc[4][8][4];
    #pragma unroll
    for (int i = 0; i < 4; i++)
        #pragma unroll
        for (int j = 0; j < 8; j++)
            #pragma unroll
            for (int k = 0; k < 4; k++) acc[i][j][k] = 0.0f;

    issue(0, 0); CP_COMMIT();
    issue(1, 1); CP_COMMIT();

    const uint32_t aOff = (wm + (lane & 15)) * SROW + (lane >> 4) * 16;
    const uint32_t bOff = A_BYTES + (wn + (lane & 7) + ((lane & 16) >> 1)) * SROW
                        + ((lane >> 3) & 1) * 16;

    int sRd = 0, sWr = 2;
    for (int kt = 0; kt < KT; kt++) {
        CP_WAIT(1);                 // stage kt arrived
        __syncthreads();            // all warps done reading stage being overwritten

        const uint32_t st = sbase + sRd * STAGE_BYTES;

        uint32_t ra[2][4][4], rb[2][4][4];
        load_frags(st, aOff, bOff, 0, ra[0], rb[0]);   // first frags before LSU flood

        if (kt + 2 < KT) issue(kt + 2, sWr);
        CP_COMMIT();                // unconditional: keeps wait_group counting safe

        #pragma unroll
        for (int ks = 0; ks < 4; ks++) {
            const int cur = ks & 1;
            if (ks < 3)
                load_frags(st, aOff, bOff, ks + 1, ra[cur ^ 1], rb[cur ^ 1]);
            #pragma unroll
            for (int mi = 0; mi < 4; mi++)
                #pragma unroll
                for (int ni = 0; ni < 8; ni++)
                    mma16816(acc[mi][ni], ra[cur][mi], &rb[cur][ni >> 1][(ni & 1) * 2]);
        }

        if (++sRd == NSTG) sRd = 0;
        if (++sWr == NSTG) sWr = 0;
    }

    // ---------------- epilogue ----------------
    #pragma unroll
    for (int mi = 0; mi < 4; mi++) {
        const int r0 = bm + wm + mi * 16 + (lane >> 2);
        #pragma unroll
        for (int ni = 0; ni < 8; ni++) {
            const int cl = wn + ni * 8 + (lane & 3) * 2;
            float v00 = acc[mi][ni][0], v01 = acc[mi][ni][1];
            float v10 = acc[mi][ni][2], v11 = acc[mi][ni][3];
            if (mode == 0) {
                float* C = (float*)Cout + (size_t)b * strideC;
                float2* p0 = (float2*)(C + (size_t)r0 * N + bn + cl);
                float2* p1 = (float2*)(C + (size_t)(r0 + 8) * N + bn + cl);
                *p0 = make_float2(v00 * scale, v01 * scale);
                *p1 = make_float2(v10 * scale, v11 * scale);
            } else if (mode == 1) {
                __nv_bfloat16* D = (__nv_bfloat16*)Cout + (size_t)b * strideC;
                #pragma unroll
                for (int rr = 0; rr < 2; rr++) {
                    float a0 = rr ? v10 : v00, a1 = rr ? v11 : v01;
                    __nv_bfloat16 h0 = __float2bfloat16(a0), h1 = __float2bfloat16(a1);
                    __nv_bfloat16 l0 = __float2bfloat16(a0 - __bfloat162float(h0));
                    __nv_bfloat16 l1 = __float2bfloat16(a1 - __bfloat162float(h1));
                    __nv_bfloat16* d = D + (size_t)(r0 + rr * 8) * 2048 + bn + cl;
                    *(uint32_t*)d          = pk2(h0, h1);
                    *(uint32_t*)(d + 1024) = pk2(l0, l1);
                }
            } else {
                const int g = bn + cl;
                const int region = g >> 10;
                const int c = g & 1023;
                #pragma unroll
                for (int rr = 0; rr < 2; rr++) {
                    float a0 = rr ? v10 : v00, a1 = rr ? v11 : v01;
                    const size_t row = (size_t)(r0 + rr * 8);
                    if (region == 2) {
                        *(float2*)(vbuf + row * 1024 + c) = make_float2(a0, a1);
                    } else {
                        __nv_bfloat16 h0 = __float2bfloat16(a0), h1 = __float2bfloat16(a1);
                        __nv_bfloat16 l0 = __float2bfloat16(a0 - __bfloat162float(h0));
                        __nv_bfloat16 l1 = __float2bfloat16(a1 - __bfloat162float(h1));
                        __nv_bfloat16* base = (region == 0) ? q2 : k2;
                        __nv_bfloat16* d = base + row * 2048 + c;
                        *(uint32_t*)d          = pk2(h0, h1);
                        *(uint32_t*)(d + 1024) = pk2(l0, l1);
                    }
                }
            }
        }
    }
}

// ---------------- conversions (dedup [hi|lo] layout) ----------------
__device__ __forceinline__ void split8_store(const float* s, __nv_bfloat16* d, int K) {
    float4 a = *(const float4*)s;
    float4 b = *(const float4*)(s + 4);
    __nv_bfloat16 h[8], l[8];
    float v[8] = {a.x, a.y, a.z, a.w, b.x, b.y, b.z, b.w};
    #pragma unroll
    for (int i = 0; i < 8; i++) {
        h[i] = __float2bfloat16(v[i]);
        l[i] = __float2bfloat16(v[i] - __bfloat162float(h[i]));
    }
    *(uint4*)d       = make_uint4(pk2(h[0], h[1]), pk2(h[2], h[3]), pk2(h[4], h[5]), pk2(h[6], h[7]));
    *(uint4*)(d + K) = make_uint4(pk2(l[0], l[1]), pk2(l[2], l[3]), pk2(l[4], l[5]), pk2(l[6], l[7]));
}

__global__ void conv_x_kernel(const float* __restrict__ x, __nv_bfloat16* __restrict__ x2)
{
    int i = blockIdx.x * blockDim.x + threadIdx.x;
    int idx = i * 8;
    int row = idx >> 10;
    int k   = idx & 1023;
    split8_store(x + (size_t)row * 1024 + k, x2 + (size_t)row * 2048 + k, 1024);
}

__global__ void conv_w_kernel(const float* __restrict__ Wq, const float* __restrict__ Wk,
                              const float* __restrict__ Wv, const float* __restrict__ Wo,
                              __nv_bfloat16* __restrict__ Wall2, __nv_bfloat16* __restrict__ Wo2)
{
    const int slice = blockIdx.y;
    const float* src = (slice == 0) ? Wq : (slice == 1) ? Wk : (slice == 2) ? Wv : Wo;
    __nv_bfloat16* dst = (slice < 3) ? Wall2 + (size_t)slice * 1024 * 2048 : Wo2;
    int i = blockIdx.x * blockDim.x + threadIdx.x;
    int idx = i * 8;
    int row = idx >> 10;
    int k   = idx & 1023;
    split8_store(src + (size_t)row * 1024 + k, dst + (size_t)row * 2048 + k, 1024);
}

// V transpose + split:  v2T[b][j] = [hi(t) | lo(t)+2048], ld 4096
__global__ void conv_vT_kernel(const float* __restrict__ vbuf,
                               __nv_bfloat16* __restrict__ v2T)
{
    __shared__ float tile[32][33];
    const int b  = blockIdx.z;
    const int t0 = blockIdx.x * 32;
    const int j0 = blockIdx.y * 32;
    const int tx = threadIdx.x, ty = threadIdx.y;   // 32 x 8

    #pragma unroll
    for (int i = 0; i < 32; i += 8)
        tile[ty + i][tx] = vbuf[((size_t)(b * S_LEN + t0 + ty + i)) * DMODEL + j0 + tx];
    __syncthreads();

    #pragma unroll
    for (int i = 0; i < 32; i += 8) {
        int j = j0 + ty + i;
        int t = t0 + tx;
        float a = tile[tx][ty + i];
        __nv_bfloat16 hi = __float2bfloat16(a);
        __nv_bfloat16 lo = __float2bfloat16(a - __bfloat162float(hi));
        __nv_bfloat16* d = v2T + ((size_t)b * DMODEL + j) * 4096 + t;
        d[0] = hi; d[2048] = lo;
    }
}

// softmax over rows; write attn2 dedup [hi|lo], ld 4096
__global__ void softmax_kernel(const float* __restrict__ dist,
                               __nv_bfloat16* __restrict__ attn2)
{
    const int row = blockIdx.x;
    const int tid = threadIdx.x;                  // 256
    const float4* d4 = (const float4*)(dist + (size_t)row * S_LEN) + tid * 2;
    float4 v0 = d4[0], v1 = d4[1];
    float v[8] = {v0.x, v0.y, v0.z, v0.w, v1.x, v1.y, v1.z, v1.w};

    float m = v[0];
    #pragma unroll
    for (int i = 1; i < 8; i++) m = fmaxf(m, v[i]);
    __shared__ float red[8];
    #pragma unroll
    for (int o = 16; o; o >>= 1) m = fmaxf(m, __shfl_xor_sync(0xffffffffu, m, o));
    if ((tid & 31) == 0) red[tid >> 5] = m;
    __syncthreads();
    m = red[0];
    #pragma unroll
    for (int i = 1; i < 8; i++) m = fmaxf(m, red[i]);
    __syncthreads();

    float s = 0.0f;
    #pragma unroll
    for (int i = 0; i < 8; i++) { v[i] = __expf(v[i] - m); s += v[i]; }
    #pragma unroll
    for (int o = 16; o; o >>= 1) s += __shfl_xor_sync(0xffffffffu, s, o);
    if ((tid & 31) == 0) red[tid >> 5] = s;
    __syncthreads();
    float tot = 0.0f;
    #pragma unroll
    for (int i = 0; i < 8; i++) tot += red[i];
    const float inv = 1.0f / tot;

    uint32_t H[4], L[4];
    #pragma unroll
    for (int i = 0; i < 4; i++) {
        float p0 = v[2 * i] * inv, p1 = v[2 * i + 1] * inv;
        __nv_bfloat16 h0 = __float2bfloat16(p0), h1 = __float2bfloat16(p1);
        __nv_bfloat16 l0 = __float2bfloat16(p0 - __bfloat162float(h0));
        __nv_bfloat16 l1 = __float2bfloat16(p1 - __bfloat162float(h1));
        H[i] = pk2(h0, h1); L[i] = pk2(l0, l1);
    }
    __nv_bfloat16* a2 = attn2 + (size_t)row * 4096 + tid * 8;
    *(uint4*)(a2)        = make_uint4(H[0], H[1], H[2], H[3]);
    *(uint4*)(a2 + 2048) = make_uint4(L[0], L[1], L[2], L[3]);
}

// ---------------- launch ----------------
extern "C" void kernel_launch(void* const* d_in, const int* in_sizes, int n_in,
                              void* d_out, int out_size)
{
    (void)in_sizes; (void)n_in; (void)out_size;
    const float* x  = (const float*)d_in[0];
    const float* Wq = (const float*)d_in[1];
    const float* Wk = (const float*)d_in[2];
    const float* Wv = (const float*)d_in[3];
    const float* Wo = (const float*)d_in[4];

    float* out    = (float*)d_out;                       // [4,2048,1024]
    float* weight = out + (size_t)MTOT * DMODEL;         // [4,2048,2048]

    void *p_x2, *p_Wall2, *p_Wo2, *p_q2, *p_k2, *p_vbuf, *p_v2T, *p_attn2, *p_ctx2;
    cudaGetSymbolAddress(&p_x2,    g_x2);
    cudaGetSymbolAddress(&p_Wall2, g_Wall2);
    cudaGetSymbolAddress(&p_Wo2,   g_Wo2);
    cudaGetSymbolAddress(&p_q2,    g_q2);
    cudaGetSymbolAddress(&p_k2,    g_k2);
    cudaGetSymbolAddress(&p_vbuf,  g_vbuf);
    cudaGetSymbolAddress(&p_v2T,   g_v2T);
    cudaGetSymbolAddress(&p_attn2, g_attn2);
    cudaGetSymbolAddress(&p_ctx2,  g_ctx2);

    __nv_bfloat16* x2    = (__nv_bfloat16*)p_x2;
    __nv_bfloat16* Wall2 = (__nv_bfloat16*)p_Wall2;
    __nv_bfloat16* Wo2   = (__nv_bfloat16*)p_Wo2;
    __nv_bfloat16* q2    = (__nv_bfloat16*)p_q2;
    __nv_bfloat16* k2    = (__nv_bfloat16*)p_k2;
    float*         vbuf  = (float*)p_vbuf;
    __nv_bfloat16* v2T   = (__nv_bfloat16*)p_v2T;
    __nv_bfloat16* attn2 = (__nv_bfloat16*)p_attn2;
    __nv_bfloat16* ctx2  = (__nv_bfloat16*)p_ctx2;

    cudaFuncSetAttribute(gemm_bf16, cudaFuncAttributeMaxDynamicSharedMemorySize, GEMM_SMEM);

    const float dist_scale = 0.044194173824159223f;   // (1024/2)^-0.5

    // 1) split-convert inputs (dedup layouts)
    conv_x_kernel<<<MTOT * DMODEL / 8 / 256, 256>>>(x, x2);
    conv_w_kernel<<<dim3(1024 * 1024 / 8 / 256, 4), 256>>>(Wq, Wk, Wv, Wo, Wall2, Wo2);

    // 2) QKV fused: x2 @ Wall2^T -> q2, k2 (dedup split), vbuf (fp32)
    gemm_bf16<<<dim3(3072 / BN, MTOT / BM, 1), 128, GEMM_SMEM>>>(
        x2, Wall2, nullptr, q2, k2, vbuf, K1, 3072, 0, 0, 0, 1.0f, 2);

    // 3) v transpose + split
    conv_vT_kernel<<<dim3(S_LEN / 32, DMODEL / 32, BATCH), dim3(32, 8)>>>(vbuf, v2T);

    // 4) weight = scale * q @ k^T   [4][2048][2048]
    gemm_bf16<<<dim3(S_LEN / BN, S_LEN / BM, BATCH), 128, GEMM_SMEM>>>(
        q2, k2, weight, nullptr, nullptr, nullptr, K1, S_LEN,
        (long long)S_LEN * 2048, (long long)S_LEN * 2048, (long long)S_LEN * S_LEN,
        dist_scale, 0);

    // 5) softmax rows -> attn2 (dedup split)
    softmax_kernel<<<MTOT, 256>>>(weight, attn2);

    // 6) ctx2 = attn @ v -> dedup split   [2048 x 1024] per batch
    gemm_bf16<<<dim3(DMODEL / BN, S_LEN / BM, BATCH), 128, GEMM_SMEM>>>(
        attn2, v2T, ctx2, nullptr, nullptr, nullptr, K2, DMODEL,
        (long long)S_LEN * 4096, (long long)DMODEL * 4096, (long long)S_LEN * 2048,
        1.0f, 1);

    // 7) out = ctx @ Wo^T  [8192 x 1024]
    gemm_bf16<<<dim3(DMODEL / BN, MTOT / BM, 1), 128, GEMM_SMEM>>>(
        ctx2, Wo2, out, nullptr, nullptr, nullptr, K1, DMODEL, 0, 0, 0, 1.0f, 0);
}